// round 12
// baseline (speedup 1.0000x reference)
#include <cuda_runtime.h>
#include <cuda_fp16.h>
#include <math.h>
#include <float.h>
#include <stdint.h>

#define Bb  8
#define Cc  256
#define HH  160
#define WW  160
#define HDs 40
#define WDs 40
#define NT  1600
#define MT  (Bb*NT)
#define SA  40              // smem row stride (halves) for [r][k] GEMM tiles
#define ASW (64*SA)
#define BSW 5120
#define SQ  264             // smem row stride for Q/K/V tiles (256+8)
#define SP  72              // smem row stride for P tile (64+8)
#define NCH 25              // kv chunks of 64
// fattn smem layout (halves)
#define OFF_Q 0
#define OFF_K (32*SQ)                 // 8448
#define OFF_V (OFF_K + 64*SQ)         // 25344
#define OFF_P (OFF_V + 64*SQ)         // 42240
#define FATTN_HALVES (OFF_P + 32*SP)  // 44544
#define FATTN_SMEM (FATTN_HALVES*2 + 160*4)   // + rpart[128], rinv[32] floats

// ---------------- static scratch ----------------
__device__ __align__(256) __half g_ds_rgb[(size_t)Bb*NT*Cc];     // token-major [b][n][c]
__device__ __align__(256) __half g_ds_ir [(size_t)Bb*NT*Cc];
__device__ __align__(256) __half g_tok[6][(size_t)MT*Cc];        // [b*NT+n][c]
__device__ __align__(256) __half g_zcat[(size_t)MT*2*Cc];        // [b*NT+n][2C]
__device__ __align__(256) __half g_wh[655360];                   // fp16 weights
__device__ float g_pre[3][(size_t)MT*Cc];
__device__ float g_fused[(size_t)Bb*Cc*NT];

__device__ __forceinline__ void cpa16u(uint32_t smem_dst, const void* gsrc) {
    asm volatile("cp.async.cg.shared.global [%0], [%1], 16;" :: "r"(smem_dst), "l"(gsrc));
}
__device__ __forceinline__ void ldsm_x4u(unsigned* r, uint32_t s) {
    asm volatile("ldmatrix.sync.aligned.m8n8.x4.shared.b16 {%0,%1,%2,%3}, [%4];"
                 : "=r"(r[0]), "=r"(r[1]), "=r"(r[2]), "=r"(r[3]) : "r"(s));
}
__device__ __forceinline__ void ldsm_x4tu(unsigned* r, uint32_t s) {
    asm volatile("ldmatrix.sync.aligned.m8n8.x4.trans.shared.b16 {%0,%1,%2,%3}, [%4];"
                 : "=r"(r[0]), "=r"(r[1]), "=r"(r[2]), "=r"(r[3]) : "r"(s));
}
__device__ __forceinline__ void hmma(float* d, const unsigned* a, unsigned b0, unsigned b1) {
    asm volatile("mma.sync.aligned.m16n8k16.row.col.f32.f16.f16.f32 "
                 "{%0,%1,%2,%3}, {%4,%5,%6,%7}, {%8,%9}, {%0,%1,%2,%3};"
                 : "+f"(d[0]), "+f"(d[1]), "+f"(d[2]), "+f"(d[3])
                 : "r"(a[0]), "r"(a[1]), "r"(a[2]), "r"(a[3]), "r"(b0), "r"(b1));
}

// ======== fp16 GEMM core (proj/final): 64x128 block, 128 thr, 3-stage ========
__device__ __forceinline__ void gemm64_fp16(
    const __half* __restrict__ A, int lda,
    const __half* __restrict__ B, int ldb,
    int K, float acc[2][8][4])
{
    __shared__ __align__(16) __half As[3][ASW];
    __shared__ __align__(16) __half Bs[3][BSW];
    const int tid = threadIdx.x, lane = tid & 31, warp = tid >> 5;
    const int wm = (warp >> 1) * 32, wn = (warp & 1) * 64;

    const int a_row = tid >> 2, a_kg = (tid & 3) * 8;
    const uint32_t as_b = (uint32_t)__cvta_generic_to_shared(&As[0][0]);
    const uint32_t bs_b = (uint32_t)__cvta_generic_to_shared(&Bs[0][0]);
    const uint32_t a_d0 = as_b + 2 * (a_row * SA + a_kg);
    const uint32_t a_d1 = a_d0 + 2 * (32 * SA);
    const uint32_t b_d0 = bs_b + 2 * (a_row * SA + a_kg);
    const uint32_t b_d1 = b_d0 + 2 * (32 * SA);
    const uint32_t b_d2 = b_d0 + 2 * (64 * SA);
    const uint32_t b_d3 = b_d0 + 2 * (96 * SA);

    auto issue = [&](int ci) {
        int k0 = ci * 32;
        uint32_t ao = (ci % 3) * (ASW * 2), bo = (ci % 3) * (BSW * 2);
        cpa16u(a_d0 + ao, A + (size_t)a_row * lda + k0 + a_kg);
        cpa16u(a_d1 + ao, A + (size_t)(a_row + 32) * lda + k0 + a_kg);
        const __half* gb = B + (size_t)a_row * ldb + k0 + a_kg;
        cpa16u(b_d0 + bo, gb);
        cpa16u(b_d1 + bo, gb + (size_t)32 * ldb);
        cpa16u(b_d2 + bo, gb + (size_t)64 * ldb);
        cpa16u(b_d3 + bo, gb + (size_t)96 * ldb);
        asm volatile("cp.async.commit_group;");
    };

    const uint32_t a_f0 = as_b + 2 * ((wm + (lane & 15)) * SA + (lane >> 4) * 8);
    const uint32_t a_f1 = a_f0 + 2 * (16 * SA);
    uint32_t b_f[4];
    {
        uint32_t base = bs_b + 2 * ((wn + (lane & 15)) * SA + (lane >> 4) * 8);
#pragma unroll
        for (int gi = 0; gi < 4; gi++) b_f[gi] = base + 2 * (gi * 16 * SA);
    }

    const int nk = K / 32;
    issue(0);
    if (nk > 1) issue(1);
    for (int i = 0; i < nk; i++) {
        if (i + 1 < nk) asm volatile("cp.async.wait_group 1;");
        else            asm volatile("cp.async.wait_group 0;");
        __syncthreads();
        if (i + 2 < nk) issue(i + 2);
        const uint32_t ao = (i % 3) * (ASW * 2), bo = (i % 3) * (BSW * 2);
#pragma unroll
        for (int s = 0; s < 2; s++) {
            const int kk = s * 16;
            unsigned a[2][4], bf[4][4];
            ldsm_x4u(a[0], a_f0 + ao + 2 * kk);
            ldsm_x4u(a[1], a_f1 + ao + 2 * kk);
#pragma unroll
            for (int gi = 0; gi < 4; gi++) ldsm_x4u(bf[gi], b_f[gi] + bo + 2 * kk);
#pragma unroll
            for (int mi = 0; mi < 2; mi++)
#pragma unroll
                for (int ni = 0; ni < 8; ni++) {
                    int gi = ni >> 1, hi = ni & 1;
                    hmma(acc[mi][ni], a[mi], bf[gi][hi], bf[gi][hi + 2]);
                }
        }
    }
}

// ---------------- weight prep ----------------
__global__ void wprep_kernel(
    const float* w0, const float* w1, const float* w2, const float* w3,
    const float* w4, const float* w5, const float* w6, const float* w7, const float* w8)
{
    int seg = blockIdx.y;
    int idx = blockIdx.x * 256 + threadIdx.x;
    int size = (seg == 8) ? 131072 : 65536;
    if (idx >= size) return;
    const float* src;
    switch (seg) {
        case 0: src = w0; break; case 1: src = w1; break; case 2: src = w2; break;
        case 3: src = w3; break; case 4: src = w4; break; case 5: src = w5; break;
        case 6: src = w6; break; case 7: src = w7; break; default: src = w8; break;
    }
    g_wh[seg * 65536 + idx] = __float2half_rn(src[idx]);
}

// ---------------- downsample: 2x2 mean -> token-major fp16 [b][n][c] ----------------
__global__ void ds_kernel(const float* __restrict__ zr, const float* __restrict__ zi) {
    __shared__ float t[32][33];
    int b = blockIdx.z, n0 = blockIdx.x * 32, c0 = blockIdx.y * 32;
    int tx = threadIdx.x, ty = threadIdx.y;
#pragma unroll
    for (int m = 0; m < 2; m++) {
        const float* src = m ? zi : zr;
        __half* dst = m ? g_ds_ir : g_ds_rgb;
        if (m) __syncthreads();
#pragma unroll
        for (int i = 0; i < 4; i++) {
            int n = n0 + tx, c = c0 + ty + 8 * i;
            int ho = n / WDs, wo = n % WDs;
            const float* p = src + ((size_t)(b * Cc + c) * HH + 4 * ho + 1) * WW + 4 * wo + 1;
            t[tx][ty + 8 * i] = 0.25f * (p[0] + p[1] + p[WW] + p[WW + 1]);
        }
        __syncthreads();
#pragma unroll
        for (int i = 0; i < 4; i++) {
            int n = n0 + ty + 8 * i, c = c0 + tx;
            dst[((size_t)b * NT + n) * Cc + c] = __float2half_rn(t[ty + 8 * i][tx]);
        }
    }
}

// ---------------- projections ----------------
__global__ void __launch_bounds__(128) proj_gemm(
    const float* __restrict__ bq_rgb, const float* __restrict__ bk_ir,
    const float* __restrict__ bv_ir,  const float* __restrict__ bq_ir,
    const float* __restrict__ bk_rgb, const float* __restrict__ bv_rgb)
{
    int b = blockIdx.x / 25, mloc = (blockIdx.x % 25) * 64;
    int n0 = blockIdx.y * 128, p = blockIdx.z;
    const __half* Ain = (p == 0 || p == 4 || p == 5) ? g_ds_rgb : g_ds_ir;
    const float* bias;
    switch (p) {
        case 0: bias = bq_rgb; break; case 1: bias = bk_ir;  break;
        case 2: bias = bv_ir;  break; case 3: bias = bq_ir;  break;
        case 4: bias = bk_rgb; break; default: bias = bv_rgb; break;
    }
    const __half* A = Ain + ((size_t)b * NT + mloc) * Cc;
    const __half* W = g_wh + p * 65536 + (size_t)n0 * Cc;
    float acc[2][8][4] = {};
    gemm64_fp16(A, Cc, W, Cc, Cc, acc);

    const int tid = threadIdx.x, lane = tid & 31, warp = tid >> 5;
    const int wm = (warp >> 1) * 32, wn = (warp & 1) * 64;
    const int g = lane >> 2, tg = lane & 3;
    __half* out = g_tok[p] + ((size_t)b * NT + mloc) * Cc + n0;
#pragma unroll
    for (int mi = 0; mi < 2; mi++) {
        int r0 = wm + mi * 16 + g;
#pragma unroll
        for (int ni = 0; ni < 8; ni++) {
            int col = wn + ni * 8 + 2 * tg;
            float b0 = bias[n0 + col], b1 = bias[n0 + col + 1];
            *(__half2*)(out + (size_t)r0 * Cc + col) =
                __floats2half2_rn(acc[mi][ni][0] + b0, acc[mi][ni][1] + b1);
            *(__half2*)(out + (size_t)(r0 + 8) * Cc + col) =
                __floats2half2_rn(acc[mi][ni][2] + b0, acc[mi][ni][3] + b1);
        }
    }
}

// ======== fused attention v2: 32 q-rows/CTA, 256 threads (8 warps) ========
// S warps 2m x 4n (16x16); PV warps 2m x 4n (16x64).
__global__ void __launch_bounds__(256) fattn_kernel() {
    extern __shared__ __half sh[];
    float* rpart = (float*)(sh + FATTN_HALVES);   // [4][32]
    float* rinv  = rpart + 128;                   // [32]

    const int m0 = blockIdx.x * 32;
    const int z = blockIdx.y, dir = z >> 3, b = z & 7;
    const __half* Qg = g_tok[dir ? 3 : 0] + ((size_t)b * NT + m0) * Cc;
    const __half* Kg = g_tok[dir ? 4 : 1] + (size_t)b * NT * Cc;
    const __half* Vg = g_tok[dir ? 5 : 2] + (size_t)b * NT * Cc;

    const int tid = threadIdx.x, lane = tid & 31, warp = tid >> 5;
    const int g = lane >> 2, tg = lane & 3;
    const int wms = (warp >> 2) * 16, wns = (warp & 3) * 16;   // S-phase tile
    const int pm  = (warp >> 2) * 16, pn  = (warp & 3) * 64;   // PV-phase tile

    const uint32_t shb = (uint32_t)__cvta_generic_to_shared(sh);
    const uint32_t qb = shb, kb = shb + OFF_K * 2, vb = shb + OFF_V * 2, pb = shb + OFF_P * 2;

    auto issue_K = [&](int c) {
        int t0 = c * 64;
#pragma unroll
        for (int i = 0; i < 8; i++) {
            int idx = tid + i * 256;
            int row = idx >> 5, ch = idx & 31;
            cpa16u(kb + 2 * (row * SQ + ch * 8), Kg + (size_t)(t0 + row) * Cc + ch * 8);
        }
        asm volatile("cp.async.commit_group;");
    };
    auto issue_V = [&](int c) {
        int t0 = c * 64;
#pragma unroll
        for (int i = 0; i < 8; i++) {
            int idx = tid + i * 256;
            int row = idx >> 5, ch = idx & 31;
            cpa16u(vb + 2 * (row * SQ + ch * 8), Vg + (size_t)(t0 + row) * Cc + ch * 8);
        }
        asm volatile("cp.async.commit_group;");
    };

    // prologue: Q + K0 (one group), V0 (next group)
    {
#pragma unroll
        for (int i = 0; i < 4; i++) {
            int idx = tid + i * 256;
            int row = idx >> 5, ch = idx & 31;
            cpa16u(qb + 2 * (row * SQ + ch * 8), Qg + (size_t)row * Cc + ch * 8);
        }
        issue_K(0);
        issue_V(0);
    }

    // hoisted ldsm addresses
    const uint32_t qa = qb + 2 * ((wms + (lane & 15)) * SQ + (lane >> 4) * 8);
    const uint32_t ka = kb + 2 * ((wns + (lane & 15)) * SQ + (lane >> 4) * 8);
    const uint32_t pa = pb + 2 * ((pm + (lane & 15)) * SP + (lane >> 4) * 8);
    uint32_t va[4];
#pragma unroll
    for (int gi = 0; gi < 4; gi++)
        va[gi] = vb + 2 * (((lane & 7) + 8 * (lane >> 4)) * SQ
                           + pn + gi * 16 + 8 * ((lane >> 3) & 1));

    float o[8][4] = {};
    float rs0 = 0.f, rs1 = 0.f;

    for (int c = 0; c < NCH; c++) {
        // ---- wait K_c, compute S (16x16 per warp) ----
        asm volatile("cp.async.wait_group 1;");
        __syncthreads();
        float s[2][4] = {};
#pragma unroll
        for (int ks = 0; ks < 16; ks++) {
            const uint32_t ko = 2 * (ks * 16);
            unsigned aq[4], bk[4];
            ldsm_x4u(aq, qa + ko);
            ldsm_x4u(bk, ka + ko);
            hmma(s[0], aq, bk[0], bk[2]);
            hmma(s[1], aq, bk[1], bk[3]);
        }
        // ---- exp, rowsum partials, store P (fp16) ----
        {
            int r0 = wms + g;
            float p0 = 0.f, p1 = 0.f;
#pragma unroll
            for (int ni = 0; ni < 2; ni++) {
                int col = wns + ni * 8 + 2 * tg;
                float e0 = __expf(s[ni][0] * 0.0625f);
                float e1 = __expf(s[ni][1] * 0.0625f);
                float e2 = __expf(s[ni][2] * 0.0625f);
                float e3 = __expf(s[ni][3] * 0.0625f);
                *(__half2*)&sh[OFF_P + r0 * SP + col] = __floats2half2_rn(e0, e1);
                *(__half2*)&sh[OFF_P + (r0 + 8) * SP + col] = __floats2half2_rn(e2, e3);
                p0 += e0 + e1;
                p1 += e2 + e3;
            }
            rs0 += p0;
            rs1 += p1;
        }
        __syncthreads();          // P complete; K_c reads done
        if (c + 1 < NCH) issue_K(c + 1);
        // ---- wait V_c, compute O += P @ V (16x64 per warp) ----
        if (c + 1 < NCH) asm volatile("cp.async.wait_group 1;");
        else             asm volatile("cp.async.wait_group 0;");
        __syncthreads();
#pragma unroll
        for (int ks = 0; ks < 4; ks++) {
            unsigned ap[4], bv[4][4];
            ldsm_x4u(ap, pa + 2 * (ks * 16));
#pragma unroll
            for (int gi = 0; gi < 4; gi++) ldsm_x4tu(bv[gi], va[gi] + 2 * (ks * 16 * SQ));
#pragma unroll
            for (int ni = 0; ni < 8; ni++) {
                int gi = ni >> 1, hi = ni & 1;
                hmma(o[ni], ap, bv[gi][hi], bv[gi][hi + 2]);
            }
        }
        __syncthreads();          // V_c reads done
        if (c + 1 < NCH) issue_V(c + 1);
    }

    // ---- deterministic rowsum reduce: 4 partials per row ----
    rs0 += __shfl_xor_sync(0xffffffffu, rs0, 1); rs0 += __shfl_xor_sync(0xffffffffu, rs0, 2);
    rs1 += __shfl_xor_sync(0xffffffffu, rs1, 1); rs1 += __shfl_xor_sync(0xffffffffu, rs1, 2);
    if (tg == 0) {
        rpart[(warp & 3) * 32 + wms + g] = rs0;
        rpart[(warp & 3) * 32 + wms + 8 + g] = rs1;
    }
    __syncthreads();
    if (tid < 32)
        rinv[tid] = 1.0f / (rpart[tid] + rpart[32 + tid] + rpart[64 + tid] + rpart[96 + tid]);
    __syncthreads();

    // ---- normalize + store O: warp owns rows pm..pm+15, cols pn..pn+63 ----
    __half* out = g_zcat + ((size_t)b * NT + m0) * 2 * Cc + dir * Cc + pn;
#pragma unroll
    for (int ni = 0; ni < 8; ni++) {
        int col = ni * 8 + 2 * tg;
        int r0 = pm + g;
        float i0 = rinv[r0], i1 = rinv[r0 + 8];
        *(__half2*)(out + (size_t)r0 * 2 * Cc + col) =
            __floats2half2_rn(o[ni][0] * i0, o[ni][1] * i0);
        *(__half2*)(out + (size_t)(r0 + 8) * 2 * Cc + col) =
            __floats2half2_rn(o[ni][2] * i1, o[ni][3] * i1);
    }
}

// ---------------- epilogue GEMMs -> fp32 pre-activations ----------------
__global__ void __launch_bounds__(128) final_gemm(
    const float* __restrict__ brgb, const float* __restrict__ bir, const float* __restrict__ bz)
{
    int m0 = blockIdx.x * 64, n0 = blockIdx.y * 128, jj = blockIdx.z;
    const __half* A = g_zcat + (size_t)m0 * 2 * Cc + (jj == 1 ? Cc : 0);
    int Kd = (jj == 2) ? 2 * Cc : Cc;
    const __half* W    = (jj == 2) ? (g_wh + 524288) : (g_wh + (6 + jj) * 65536);
    const float* bias = (jj == 0) ? brgb : ((jj == 1) ? bir : bz);
    float acc[2][8][4] = {};
    gemm64_fp16(A, 2 * Cc, W + (size_t)n0 * Kd, Kd, Kd, acc);

    const int tid = threadIdx.x, lane = tid & 31, warp = tid >> 5;
    const int wm = (warp >> 1) * 32, wn = (warp & 1) * 64;
    const int g = lane >> 2, tg = lane & 3;
    float* out = g_pre[jj] + (size_t)m0 * Cc + n0;
#pragma unroll
    for (int mi = 0; mi < 2; mi++) {
        int r0 = wm + mi * 16 + g;
#pragma unroll
        for (int ni = 0; ni < 8; ni++) {
            int col = wn + ni * 8 + 2 * tg;
            float b0 = bias[n0 + col], b1 = bias[n0 + col + 1];
            float2 v0 = { acc[mi][ni][0] + b0, acc[mi][ni][1] + b1 };
            float2 v1 = { acc[mi][ni][2] + b0, acc[mi][ni][3] + b1 };
            *(float2*)(out + (size_t)r0 * Cc + col) = v0;
            *(float2*)(out + (size_t)(r0 + 8) * Cc + col) = v1;
        }
    }
}

// ---------------- gate fuse + smem transpose to [B,C,N] ----------------
__global__ void fuse_kernel(const int* __restrict__ time_idx, const float* __restrict__ temb) {
    __shared__ float t[32][33];
    int b = blockIdx.z;
    int n0 = blockIdx.x * 32, c0 = blockIdx.y * 32;
    int tx = threadIdx.x, ty = threadIdx.y;
    int ti = time_idx[b];
#pragma unroll
    for (int i = 0; i < 4; i++) {
        int n = n0 + ty + 8 * i, c = c0 + tx;
        size_t m = ((size_t)b * NT + n) * Cc + c;
        float hr = tanhf(g_pre[0][m]);
        float hi = tanhf(g_pre[1][m]);
        float zb = 1.0f / (1.0f + __expf(-g_pre[2][m]));
        float te = temb[ti * Cc + c];
        float zf = 1.0f / (1.0f + __expf(-(zb + te)));
        t[ty + 8 * i][tx] = zf * hr + (1.0f - zf) * hi;
    }
    __syncthreads();
#pragma unroll
    for (int i = 0; i < 4; i++) {
        int c = c0 + ty + 8 * i, n = n0 + tx;
        g_fused[((size_t)b * Cc + c) * NT + n] = t[tx][ty + 8 * i];
    }
}

// ---------------- bilinear upsample 40 -> 160 ----------------
__global__ void upsample_kernel(float* __restrict__ out) {
    int idx = blockIdx.x * blockDim.x + threadIdx.x;
    if (idx >= Bb*Cc*HH*WW) return;
    int w  = idx % WW;
    int h  = (idx / WW) % HH;
    int bc = idx / (HH * WW);
    float sh = fmaxf(h * 0.25f - 0.375f, 0.0f);
    float sw = fmaxf(w * 0.25f - 0.375f, 0.0f);
    int h0 = (int)sh; float fh = sh - (float)h0; int h1 = min(h0 + 1, HDs - 1);
    int w0 = (int)sw; float fw = sw - (float)w0; int w1 = min(w0 + 1, WDs - 1);
    const float* p = g_fused + (size_t)bc * NT;
    float v00 = p[h0 * WDs + w0], v01 = p[h0 * WDs + w1];
    float v10 = p[h1 * WDs + w0], v11 = p[h1 * WDs + w1];
    float top = v00 * (1.0f - fw) + v01 * fw;
    float bot = v10 * (1.0f - fw) + v11 * fw;
    out[idx] = top * (1.0f - fh) + bot * fh;
}

extern "C" void kernel_launch(void* const* d_in, const int* in_sizes, int n_in,
                              void* d_out, int out_size) {
    const float* z_rgb  = (const float*)d_in[0];
    const float* z_ir   = (const float*)d_in[1];
    const int*   tidx   = (const int*)  d_in[2];
    const float* Wq_rgb = (const float*)d_in[3],  *bq_rgb = (const float*)d_in[4];
    const float* Wk_ir  = (const float*)d_in[5],  *bk_ir  = (const float*)d_in[6];
    const float* Wv_ir  = (const float*)d_in[7],  *bv_ir  = (const float*)d_in[8];
    const float* Wq_ir  = (const float*)d_in[9],  *bq_ir  = (const float*)d_in[10];
    const float* Wk_rgb = (const float*)d_in[11], *bk_rgb = (const float*)d_in[12];
    const float* Wv_rgb = (const float*)d_in[13], *bv_rgb = (const float*)d_in[14];
    const float* Wrgb   = (const float*)d_in[15], *brgb   = (const float*)d_in[16];
    const float* Wir    = (const float*)d_in[17], *bir    = (const float*)d_in[18];
    const float* Wz     = (const float*)d_in[19], *bz     = (const float*)d_in[20];
    const float* temb   = (const float*)d_in[21];

    static bool attr_done = false;
    if (!attr_done) {
        cudaFuncSetAttribute(fattn_kernel, cudaFuncAttributeMaxDynamicSharedMemorySize, FATTN_SMEM);
        attr_done = true;
    }

    wprep_kernel<<<dim3(512, 9), 256>>>(Wq_rgb, Wk_ir, Wv_ir, Wq_ir, Wk_rgb, Wv_rgb,
                                        Wrgb, Wir, Wz);
    ds_kernel<<<dim3(50, 8, 8), dim3(32, 8)>>>(z_rgb, z_ir);
    proj_gemm<<<dim3(200, 2, 6), 128>>>(bq_rgb, bk_ir, bv_ir, bq_ir, bk_rgb, bv_rgb);
    fattn_kernel<<<dim3(50, 16), 256, FATTN_SMEM>>>();
    final_gemm<<<dim3(200, 2, 3), 128>>>(brgb, bir, bz);
    fuse_kernel<<<dim3(NT/32, Cc/32, Bb), dim3(32, 8)>>>(tidx, temb);
    upsample_kernel<<<(Bb*Cc*HH*WW + 255) / 256, 256>>>((float*)d_out);
}

// round 13
// speedup vs baseline: 1.0743x; 1.0743x over previous
#include <cuda_runtime.h>
#include <cuda_fp16.h>
#include <math.h>
#include <float.h>
#include <stdint.h>

#define Bb  8
#define Cc  256
#define HH  160
#define WW  160
#define HDs 40
#define WDs 40
#define NT  1600
#define MT  (Bb*NT)
#define ATW 1664            // padded attention width (13*128)
#define NBLK 13
#define SA  40              // smem row stride (halves) for [r][k] tiles
#define SN  136             // smem row stride (halves) for [k][n] tiles (128+8)
#define ASW (64*SA)
#define BSW 5120
#define GSW (64*SA)         // gatefuse per-tile halves

// ---------------- static scratch ----------------
__device__ __align__(256) __half g_ds_rgb[(size_t)Bb*NT*Cc];     // token-major [b][n][c]
__device__ __align__(256) __half g_ds_ir [(size_t)Bb*NT*Cc];
__device__ __align__(256) __half g_tok[6][(size_t)(MT+64)*Cc];   // [b*NT+n][c] (+zero tail)
__device__ __align__(256) __half g_attn0[(size_t)MT*ATW];        // exp(scores), pad cols 0
__device__ __align__(256) __half g_attn1[(size_t)MT*ATW];
__device__ __align__(256) __half g_zcat[(size_t)MT*2*Cc];        // [b*NT+n][2C]
__device__ __align__(256) __half g_wh[655360];                   // fp16 weights
__device__ float g_psum[2*Bb*NT*NBLK];
__device__ float g_rowinv[2*Bb*NT];
__device__ float g_fused[(size_t)Bb*Cc*NT];

__device__ __forceinline__ void cpa16u(uint32_t smem_dst, const void* gsrc) {
    asm volatile("cp.async.cg.shared.global [%0], [%1], 16;" :: "r"(smem_dst), "l"(gsrc));
}
__device__ __forceinline__ void ldsm_x4u(unsigned* r, uint32_t s) {
    asm volatile("ldmatrix.sync.aligned.m8n8.x4.shared.b16 {%0,%1,%2,%3}, [%4];"
                 : "=r"(r[0]), "=r"(r[1]), "=r"(r[2]), "=r"(r[3]) : "r"(s));
}
__device__ __forceinline__ void ldsm_x4tu(unsigned* r, uint32_t s) {
    asm volatile("ldmatrix.sync.aligned.m8n8.x4.trans.shared.b16 {%0,%1,%2,%3}, [%4];"
                 : "=r"(r[0]), "=r"(r[1]), "=r"(r[2]), "=r"(r[3]) : "r"(s));
}
__device__ __forceinline__ void hmma(float* d, const unsigned* a, unsigned b0, unsigned b1) {
    asm volatile("mma.sync.aligned.m16n8k16.row.col.f32.f16.f16.f32 "
                 "{%0,%1,%2,%3}, {%4,%5,%6,%7}, {%8,%9}, {%0,%1,%2,%3};"
                 : "+f"(d[0]), "+f"(d[1]), "+f"(d[2]), "+f"(d[3])
                 : "r"(a[0]), "r"(a[1]), "r"(a[2]), "r"(a[3]), "r"(b0), "r"(b1));
}

// ======== fp16 GEMM core: 64(M) x 128(N) block, 128 threads, 3-stage pipeline ========
// A: [m][k] halves (lda). BTRANS=0: B [n][k] (ldb). BTRANS=1: B [k][n] (ldb).
template<int BTRANS>
__device__ __forceinline__ void gemm64_fp16(
    const __half* __restrict__ A, int lda,
    const __half* __restrict__ B, int ldb,
    int K, float acc[2][8][4])
{
    __shared__ __align__(16) __half As[3][ASW];
    __shared__ __align__(16) __half Bs[3][BSW];
    const int tid = threadIdx.x, lane = tid & 31, warp = tid >> 5;
    const int wm = (warp >> 1) * 32, wn = (warp & 1) * 64;

    const int a_row = tid >> 2, a_kg = (tid & 3) * 8;
    const int bt_row = tid >> 4, bt_nc = (tid & 15) * 8;
    const uint32_t as_b = (uint32_t)__cvta_generic_to_shared(&As[0][0]);
    const uint32_t bs_b = (uint32_t)__cvta_generic_to_shared(&Bs[0][0]);
    const uint32_t a_d0 = as_b + 2 * (a_row * SA + a_kg);
    const uint32_t a_d1 = a_d0 + 2 * (32 * SA);
    uint32_t b_d0, b_d1, b_d2, b_d3;
    if (BTRANS) {
        b_d0 = bs_b + 2 * (bt_row * SN + bt_nc);
        b_d1 = b_d0 + 2 * (8 * SN);
        b_d2 = b_d0 + 2 * (16 * SN);
        b_d3 = b_d0 + 2 * (24 * SN);
    } else {
        b_d0 = bs_b + 2 * (a_row * SA + a_kg);
        b_d1 = b_d0 + 2 * (32 * SA);
        b_d2 = b_d0 + 2 * (64 * SA);
        b_d3 = b_d0 + 2 * (96 * SA);
    }

    auto issue = [&](int ci) {
        int k0 = ci * 32;
        uint32_t ao = (ci % 3) * (ASW * 2), bo = (ci % 3) * (BSW * 2);
        cpa16u(a_d0 + ao, A + (size_t)a_row * lda + k0 + a_kg);
        cpa16u(a_d1 + ao, A + (size_t)(a_row + 32) * lda + k0 + a_kg);
        if (BTRANS) {
            const __half* gb = B + (size_t)(k0 + bt_row) * ldb + bt_nc;
            cpa16u(b_d0 + bo, gb);
            cpa16u(b_d1 + bo, gb + (size_t)8 * ldb);
            cpa16u(b_d2 + bo, gb + (size_t)16 * ldb);
            cpa16u(b_d3 + bo, gb + (size_t)24 * ldb);
        } else {
            const __half* gb = B + (size_t)a_row * ldb + k0 + a_kg;
            cpa16u(b_d0 + bo, gb);
            cpa16u(b_d1 + bo, gb + (size_t)32 * ldb);
            cpa16u(b_d2 + bo, gb + (size_t)64 * ldb);
            cpa16u(b_d3 + bo, gb + (size_t)96 * ldb);
        }
        asm volatile("cp.async.commit_group;");
    };

    const uint32_t a_f0 = as_b + 2 * ((wm + (lane & 15)) * SA + (lane >> 4) * 8);
    const uint32_t a_f1 = a_f0 + 2 * (16 * SA);
    uint32_t b_f[4];
    if (BTRANS) {
        uint32_t base = bs_b + 2 * (((lane & 7) + 8 * (lane >> 4)) * SN
                                    + wn + 8 * ((lane >> 3) & 1));
#pragma unroll
        for (int gi = 0; gi < 4; gi++) b_f[gi] = base + 2 * (gi * 16);
    } else {
        uint32_t base = bs_b + 2 * ((wn + (lane & 15)) * SA + (lane >> 4) * 8);
#pragma unroll
        for (int gi = 0; gi < 4; gi++) b_f[gi] = base + 2 * (gi * 16 * SA);
    }

    const int nk = K / 32;
    issue(0);
    if (nk > 1) issue(1);
    for (int i = 0; i < nk; i++) {
        if (i + 1 < nk) asm volatile("cp.async.wait_group 1;");
        else            asm volatile("cp.async.wait_group 0;");
        __syncthreads();
        if (i + 2 < nk) issue(i + 2);
        const uint32_t ao = (i % 3) * (ASW * 2), bo = (i % 3) * (BSW * 2);
#pragma unroll
        for (int s = 0; s < 2; s++) {
            const int kk = s * 16;
            unsigned a[2][4], bf[4][4];
            ldsm_x4u(a[0], a_f0 + ao + 2 * kk);
            ldsm_x4u(a[1], a_f1 + ao + 2 * kk);
#pragma unroll
            for (int gi = 0; gi < 4; gi++) {
                if (BTRANS) ldsm_x4tu(bf[gi], b_f[gi] + bo + 2 * (kk * SN));
                else        ldsm_x4u (bf[gi], b_f[gi] + bo + 2 * kk);
            }
#pragma unroll
            for (int mi = 0; mi < 2; mi++)
#pragma unroll
                for (int ni = 0; ni < 8; ni++) {
                    int gi = ni >> 1, hi = ni & 1;
                    hmma(acc[mi][ni], a[mi], bf[gi][hi], bf[gi][hi + 2]);
                }
        }
    }
}

// ---------------- weight prep ----------------
__global__ void wprep_kernel(
    const float* w0, const float* w1, const float* w2, const float* w3,
    const float* w4, const float* w5, const float* w6, const float* w7, const float* w8)
{
    int seg = blockIdx.y;
    int idx = blockIdx.x * 256 + threadIdx.x;
    int size = (seg == 8) ? 131072 : 65536;
    if (idx >= size) return;
    const float* src;
    switch (seg) {
        case 0: src = w0; break; case 1: src = w1; break; case 2: src = w2; break;
        case 3: src = w3; break; case 4: src = w4; break; case 5: src = w5; break;
        case 6: src = w6; break; case 7: src = w7; break; default: src = w8; break;
    }
    g_wh[seg * 65536 + idx] = __float2half_rn(src[idx]);
}

// ---------------- downsample: 2x2 mean -> token-major fp16 [b][n][c] ----------------
__global__ void ds_kernel(const float* __restrict__ zr, const float* __restrict__ zi) {
    __shared__ float t[32][33];
    int b = blockIdx.z, n0 = blockIdx.x * 32, c0 = blockIdx.y * 32;
    int tx = threadIdx.x, ty = threadIdx.y;
#pragma unroll
    for (int m = 0; m < 2; m++) {
        const float* src = m ? zi : zr;
        __half* dst = m ? g_ds_ir : g_ds_rgb;
        if (m) __syncthreads();
#pragma unroll
        for (int i = 0; i < 4; i++) {
            int n = n0 + tx, c = c0 + ty + 8 * i;
            int ho = n / WDs, wo = n % WDs;
            const float* p = src + ((size_t)(b * Cc + c) * HH + 4 * ho + 1) * WW + 4 * wo + 1;
            t[tx][ty + 8 * i] = 0.25f * (p[0] + p[1] + p[WW] + p[WW + 1]);
        }
        __syncthreads();
#pragma unroll
        for (int i = 0; i < 4; i++) {
            int n = n0 + ty + 8 * i, c = c0 + tx;
            dst[((size_t)b * NT + n) * Cc + c] = __float2half_rn(t[ty + 8 * i][tx]);
        }
    }
}

// ---------------- projections ----------------
__global__ void __launch_bounds__(128) proj_gemm(
    const float* __restrict__ bq_rgb, const float* __restrict__ bk_ir,
    const float* __restrict__ bv_ir,  const float* __restrict__ bq_ir,
    const float* __restrict__ bk_rgb, const float* __restrict__ bv_rgb)
{
    int b = blockIdx.x / 25, mloc = (blockIdx.x % 25) * 64;
    int n0 = blockIdx.y * 128, p = blockIdx.z;
    const __half* Ain = (p == 0 || p == 4 || p == 5) ? g_ds_rgb : g_ds_ir;
    const float* bias;
    switch (p) {
        case 0: bias = bq_rgb; break; case 1: bias = bk_ir;  break;
        case 2: bias = bv_ir;  break; case 3: bias = bq_ir;  break;
        case 4: bias = bk_rgb; break; default: bias = bv_rgb; break;
    }
    const __half* A = Ain + ((size_t)b * NT + mloc) * Cc;
    const __half* W = g_wh + p * 65536 + (size_t)n0 * Cc;
    float acc[2][8][4] = {};
    gemm64_fp16<0>(A, Cc, W, Cc, Cc, acc);

    const int tid = threadIdx.x, lane = tid & 31, warp = tid >> 5;
    const int wm = (warp >> 1) * 32, wn = (warp & 1) * 64;
    const int g = lane >> 2, tg = lane & 3;
    __half* out = g_tok[p] + ((size_t)b * NT + mloc) * Cc + n0;
#pragma unroll
    for (int mi = 0; mi < 2; mi++) {
        int r0 = wm + mi * 16 + g;
#pragma unroll
        for (int ni = 0; ni < 8; ni++) {
            int col = wn + ni * 8 + 2 * tg;
            float b0 = bias[n0 + col], b1 = bias[n0 + col + 1];
            *(__half2*)(out + (size_t)r0 * Cc + col) =
                __floats2half2_rn(acc[mi][ni][0] + b0, acc[mi][ni][1] + b1);
            *(__half2*)(out + (size_t)(r0 + 8) * Cc + col) =
                __floats2half2_rn(acc[mi][ni][2] + b0, acc[mi][ni][3] + b1);
        }
    }
}

// ---------------- scores: attn = exp((Q K^T)/16) fp16, partial rowsums ----------------
__global__ void __launch_bounds__(128) scores_gemm() {
    __shared__ float rsum[64];
    int m0 = blockIdx.x * 64, n0 = blockIdx.y * 128;
    int z = blockIdx.z, dir = z >> 3, b = z & 7;
    const __half* Aq = g_tok[dir ? 3 : 0] + ((size_t)b * NT + m0) * Cc;
    const __half* Bk = g_tok[dir ? 4 : 1] + ((size_t)b * NT + n0) * Cc;
    __half* out = (dir ? g_attn1 : g_attn0) + ((size_t)b * NT + m0) * ATW + n0;

    if (threadIdx.x < 64) rsum[threadIdx.x] = 0.f;
    float acc[2][8][4] = {};
    gemm64_fp16<0>(Aq, Cc, Bk, Cc, Cc, acc);

    const int tid = threadIdx.x, lane = tid & 31, warp = tid >> 5;
    const int wm = (warp >> 1) * 32, wn = (warp & 1) * 64;
    const int g = lane >> 2, tg = lane & 3;
#pragma unroll
    for (int mi = 0; mi < 2; mi++) {
        int r0 = wm + mi * 16 + g;
        float p0 = 0.f, p1 = 0.f;
#pragma unroll
        for (int ni = 0; ni < 8; ni++) {
            int col = wn + ni * 8 + 2 * tg;
            bool real = (n0 + col) < NT;
            float e0 = real ? __expf(acc[mi][ni][0] * 0.0625f) : 0.f;
            float e1 = real ? __expf(acc[mi][ni][1] * 0.0625f) : 0.f;
            float e2 = real ? __expf(acc[mi][ni][2] * 0.0625f) : 0.f;
            float e3 = real ? __expf(acc[mi][ni][3] * 0.0625f) : 0.f;
            *(__half2*)(out + (size_t)r0 * ATW + col) = __floats2half2_rn(e0, e1);
            *(__half2*)(out + (size_t)(r0 + 8) * ATW + col) = __floats2half2_rn(e2, e3);
            p0 += e0 + e1;
            p1 += e2 + e3;
        }
        p0 += __shfl_xor_sync(0xffffffffu, p0, 1); p0 += __shfl_xor_sync(0xffffffffu, p0, 2);
        p1 += __shfl_xor_sync(0xffffffffu, p1, 1); p1 += __shfl_xor_sync(0xffffffffu, p1, 2);
        if (tg == 0) {
            atomicAdd(&rsum[r0], p0);
            atomicAdd(&rsum[r0 + 8], p1);
        }
    }
    __syncthreads();
    if (tid < 64)
        g_psum[((size_t)z * NT + m0 + tid) * NBLK + blockIdx.y] = rsum[tid];
}

// ---------------- rowsum reduce ----------------
__global__ void rowinv_kernel() {
    int idx = blockIdx.x * blockDim.x + threadIdx.x;
    if (idx >= 2 * Bb * NT) return;
    float s = 0.f;
    const float* p = g_psum + (size_t)idx * NBLK;
#pragma unroll
    for (int j = 0; j < NBLK; j++) s += p[j];
    g_rowinv[idx] = 1.0f / s;
}

// ---------------- attn @ V (V [k][n] via ldmatrix.trans) -> zcat ----------------
__global__ void __launch_bounds__(128) av_gemm() {
    int m0 = blockIdx.x * 64, n0 = blockIdx.y * 128;
    int z = blockIdx.z, dir = z >> 3, b = z & 7;
    const __half* P = (dir ? g_attn1 : g_attn0) + ((size_t)b * NT + m0) * ATW;
    const __half* V = g_tok[dir ? 5 : 2] + (size_t)b * NT * Cc + n0;   // [k][n], ldb=Cc
    float acc[2][8][4] = {};
    gemm64_fp16<1>(P, ATW, V, Cc, ATW, acc);

    const int tid = threadIdx.x, lane = tid & 31, warp = tid >> 5;
    const int wm = (warp >> 1) * 32, wn = (warp & 1) * 64;
    const int g = lane >> 2, tg = lane & 3;
    __half* out = g_zcat + ((size_t)b * NT + m0) * 2 * Cc + dir * Cc + n0;
    const float* rinv = g_rowinv + (size_t)z * NT + m0;
#pragma unroll
    for (int mi = 0; mi < 2; mi++) {
        int r0 = wm + mi * 16 + g;
        float i0 = rinv[r0], i1 = rinv[r0 + 8];
#pragma unroll
        for (int ni = 0; ni < 8; ni++) {
            int col = wn + ni * 8 + 2 * tg;
            *(__half2*)(out + (size_t)r0 * 2 * Cc + col) =
                __floats2half2_rn(acc[mi][ni][0] * i0, acc[mi][ni][1] * i0);
            *(__half2*)(out + (size_t)(r0 + 8) * 2 * Cc + col) =
                __floats2half2_rn(acc[mi][ni][2] * i1, acc[mi][ni][3] * i1);
        }
    }
}

// ======== fused epilogue: 3 GEMMs + gate + tanh/sigmoid + transpose -> g_fused ========
// Block tile: 64 tokens x 64 channels; 4 warps of 32x32. K = 512 over zcat.
__global__ void __launch_bounds__(128) gatefuse_kernel(
    const float* __restrict__ brgb, const float* __restrict__ bir,
    const float* __restrict__ bz,
    const int* __restrict__ time_idx, const float* __restrict__ temb)
{
    __shared__ __align__(16) __half As[3][GSW];
    __shared__ __align__(16) __half Bzs[3][GSW];
    __shared__ __align__(16) __half Bhs[3][GSW];
    __shared__ float tb[64][65];

    const int m0 = blockIdx.x * 64, n0 = blockIdx.y * 64;
    const __half* A  = g_zcat + (size_t)m0 * 2 * Cc;
    const __half* Wz = g_wh + 524288 + (size_t)n0 * 512;
    const __half* Wr = g_wh + 6 * 65536 + (size_t)n0 * 256;
    const __half* Wi = g_wh + 7 * 65536 + (size_t)n0 * 256;

    const int tid = threadIdx.x, lane = tid & 31, warp = tid >> 5;
    const int wm = (warp >> 1) * 32, wn = (warp & 1) * 32;
    const int g = lane >> 2, tg = lane & 3;

    const int row = tid >> 2, kg = (tid & 3) * 8;
    const uint32_t as_b  = (uint32_t)__cvta_generic_to_shared(&As[0][0]);
    const uint32_t bzs_b = (uint32_t)__cvta_generic_to_shared(&Bzs[0][0]);
    const uint32_t bhs_b = (uint32_t)__cvta_generic_to_shared(&Bhs[0][0]);
    const uint32_t a_d0  = as_b  + 2 * (row * SA + kg), a_d1  = a_d0  + 2 * (32 * SA);
    const uint32_t bz_d0 = bzs_b + 2 * (row * SA + kg), bz_d1 = bz_d0 + 2 * (32 * SA);
    const uint32_t bh_d0 = bhs_b + 2 * (row * SA + kg), bh_d1 = bh_d0 + 2 * (32 * SA);

    auto issue = [&](int ci) {
        int k0 = ci * 32;
        uint32_t off = (ci % 3) * (GSW * 2);
        cpa16u(a_d0 + off, A + (size_t)row * 512 + k0 + kg);
        cpa16u(a_d1 + off, A + (size_t)(row + 32) * 512 + k0 + kg);
        cpa16u(bz_d0 + off, Wz + (size_t)row * 512 + k0 + kg);
        cpa16u(bz_d1 + off, Wz + (size_t)(row + 32) * 512 + k0 + kg);
        const __half* Wh = (k0 < 256) ? (Wr + k0) : (Wi + k0 - 256);
        cpa16u(bh_d0 + off, Wh + (size_t)row * 256 + kg);
        cpa16u(bh_d1 + off, Wh + (size_t)(row + 32) * 256 + kg);
        asm volatile("cp.async.commit_group;");
    };

    const uint32_t a_f0  = as_b  + 2 * ((wm + (lane & 15)) * SA + (lane >> 4) * 8);
    const uint32_t a_f1  = a_f0 + 2 * (16 * SA);
    const uint32_t bz_f0 = bzs_b + 2 * ((wn + (lane & 15)) * SA + (lane >> 4) * 8);
    const uint32_t bz_f1 = bz_f0 + 2 * (16 * SA);
    const uint32_t bh_f0 = bhs_b + 2 * ((wn + (lane & 15)) * SA + (lane >> 4) * 8);
    const uint32_t bh_f1 = bh_f0 + 2 * (16 * SA);

    float acc_z[2][4][4] = {}, acc_hr[2][4][4] = {}, acc_hi[2][4][4] = {};

    issue(0); issue(1);
    for (int i = 0; i < 16; i++) {
        if (i + 1 < 16) asm volatile("cp.async.wait_group 1;");
        else            asm volatile("cp.async.wait_group 0;");
        __syncthreads();
        if (i + 2 < 16) issue(i + 2);
        const uint32_t off = (i % 3) * (GSW * 2);
#pragma unroll
        for (int s = 0; s < 2; s++) {
            const uint32_t ko = off + 2 * (s * 16);
            unsigned a[2][4], zf[2][4], hf[2][4];
            ldsm_x4u(a[0], a_f0 + ko);  ldsm_x4u(a[1], a_f1 + ko);
            ldsm_x4u(zf[0], bz_f0 + ko); ldsm_x4u(zf[1], bz_f1 + ko);
            ldsm_x4u(hf[0], bh_f0 + ko); ldsm_x4u(hf[1], bh_f1 + ko);
#pragma unroll
            for (int mi = 0; mi < 2; mi++)
#pragma unroll
                for (int nj = 0; nj < 4; nj++) {
                    int gi = nj >> 1, hi = nj & 1;
                    hmma(acc_z[mi][nj], a[mi], zf[gi][hi], zf[gi][hi + 2]);
                }
            if (i < 8) {
#pragma unroll
                for (int mi = 0; mi < 2; mi++)
#pragma unroll
                    for (int nj = 0; nj < 4; nj++) {
                        int gi = nj >> 1, hi = nj & 1;
                        hmma(acc_hr[mi][nj], a[mi], hf[gi][hi], hf[gi][hi + 2]);
                    }
            } else {
#pragma unroll
                for (int mi = 0; mi < 2; mi++)
#pragma unroll
                    for (int nj = 0; nj < 4; nj++) {
                        int gi = nj >> 1, hi = nj & 1;
                        hmma(acc_hi[mi][nj], a[mi], hf[gi][hi], hf[gi][hi + 2]);
                    }
            }
        }
    }

    const int bI = m0 / NT, nt0 = m0 % NT;
    const int ti = time_idx[bI];
#pragma unroll
    for (int mi = 0; mi < 2; mi++)
#pragma unroll
        for (int nj = 0; nj < 4; nj++)
#pragma unroll
            for (int e = 0; e < 4; e++) {
                int r = wm + mi * 16 + g + ((e >> 1) ? 8 : 0);
                int c = wn + nj * 8 + 2 * tg + (e & 1);
                float hr = tanhf(acc_hr[mi][nj][e] + brgb[n0 + c]);
                float hi = tanhf(acc_hi[mi][nj][e] + bir[n0 + c]);
                float zb = 1.0f / (1.0f + __expf(-(acc_z[mi][nj][e] + bz[n0 + c])));
                float zg = 1.0f / (1.0f + __expf(-(zb + temb[ti * Cc + n0 + c])));
                tb[r][c] = zg * hr + (1.0f - zg) * hi;
            }
    __syncthreads();
    // coalesced writeout: g_fused[(b*Cc + c)*NT + nt0 + tok]
#pragma unroll
    for (int q0 = 0; q0 < 8; q0++) {
        int q = tid + q0 * 128;            // 0..1023
        int c = q >> 4, ch = (q & 15) * 4;
        float4 v = make_float4(tb[ch][c], tb[ch + 1][c], tb[ch + 2][c], tb[ch + 3][c]);
        *(float4*)(g_fused + ((size_t)bI * Cc + n0 + c) * NT + nt0 + ch) = v;
    }
}

// ---------------- bilinear upsample 40 -> 160 ----------------
__global__ void upsample_kernel(float* __restrict__ out) {
    int idx = blockIdx.x * blockDim.x + threadIdx.x;
    if (idx >= Bb*Cc*HH*WW) return;
    int w  = idx % WW;
    int h  = (idx / WW) % HH;
    int bc = idx / (HH * WW);
    float sh = fmaxf(h * 0.25f - 0.375f, 0.0f);
    float sw = fmaxf(w * 0.25f - 0.375f, 0.0f);
    int h0 = (int)sh; float fh = sh - (float)h0; int h1 = min(h0 + 1, HDs - 1);
    int w0 = (int)sw; float fw = sw - (float)w0; int w1 = min(w0 + 1, WDs - 1);
    const float* p = g_fused + (size_t)bc * NT;
    float v00 = p[h0 * WDs + w0], v01 = p[h0 * WDs + w1];
    float v10 = p[h1 * WDs + w0], v11 = p[h1 * WDs + w1];
    float top = v00 * (1.0f - fw) + v01 * fw;
    float bot = v10 * (1.0f - fw) + v11 * fw;
    out[idx] = top * (1.0f - fh) + bot * fh;
}

extern "C" void kernel_launch(void* const* d_in, const int* in_sizes, int n_in,
                              void* d_out, int out_size) {
    const float* z_rgb  = (const float*)d_in[0];
    const float* z_ir   = (const float*)d_in[1];
    const int*   tidx   = (const int*)  d_in[2];
    const float* Wq_rgb = (const float*)d_in[3],  *bq_rgb = (const float*)d_in[4];
    const float* Wk_ir  = (const float*)d_in[5],  *bk_ir  = (const float*)d_in[6];
    const float* Wv_ir  = (const float*)d_in[7],  *bv_ir  = (const float*)d_in[8];
    const float* Wq_ir  = (const float*)d_in[9],  *bq_ir  = (const float*)d_in[10];
    const float* Wk_rgb = (const float*)d_in[11], *bk_rgb = (const float*)d_in[12];
    const float* Wv_rgb = (const float*)d_in[13], *bv_rgb = (const float*)d_in[14];
    const float* Wrgb   = (const float*)d_in[15], *brgb   = (const float*)d_in[16];
    const float* Wir    = (const float*)d_in[17], *bir    = (const float*)d_in[18];
    const float* Wz     = (const float*)d_in[19], *bz     = (const float*)d_in[20];
    const float* temb   = (const float*)d_in[21];

    wprep_kernel<<<dim3(512, 9), 256>>>(Wq_rgb, Wk_ir, Wv_ir, Wq_ir, Wk_rgb, Wv_rgb,
                                        Wrgb, Wir, Wz);
    ds_kernel<<<dim3(50, 8, 8), dim3(32, 8)>>>(z_rgb, z_ir);
    proj_gemm<<<dim3(200, 2, 6), 128>>>(bq_rgb, bk_ir, bv_ir, bq_ir, bk_rgb, bv_rgb);
    scores_gemm<<<dim3(25, NBLK, 16), 128>>>();
    rowinv_kernel<<<(2*Bb*NT + 255) / 256, 256>>>();
    av_gemm<<<dim3(25, 2, 16), 128>>>();
    gatefuse_kernel<<<dim3(200, 4), 128>>>(brgb, bir, bz, tidx, temb);
    upsample_kernel<<<(Bb*Cc*HH*WW + 255) / 256, 256>>>((float*)d_out);
}

// round 14
// speedup vs baseline: 1.2607x; 1.1735x over previous
#include <cuda_runtime.h>
#include <cuda_fp16.h>
#include <math.h>
#include <float.h>
#include <stdint.h>

#define Bb  8
#define Cc  256
#define HH  160
#define WW  160
#define HDs 40
#define WDs 40
#define NT  1600
#define MT  (Bb*NT)
#define ATW 1664            // padded attention width (13*128)
#define NBLK 13
#define SA  40              // smem row stride (halves) for [r][k] tiles
#define SN  136             // smem row stride (halves) for [k][n] tiles, n-width 128
#define SVN 264             // smem row stride (halves) for [k][n] tiles, n-width 256
#define ASW (64*SA)
#define BSW 5120
#define GSW (64*SA)
// av (64x256) dynamic smem: 3 stages A(64*SA) + B(32*SVN), halves
#define AV_A_ST (64*SA)
#define AV_B_ST (32*SVN)
#define AV_SMEM ((3*(AV_A_ST + AV_B_ST)) * 2)   // 66048 B

// ---------------- static scratch ----------------
__device__ __align__(256) __half g_ds_rgb[(size_t)Bb*NT*Cc];
__device__ __align__(256) __half g_ds_ir [(size_t)Bb*NT*Cc];
__device__ __align__(256) __half g_tok[6][(size_t)(MT+64)*Cc];
__device__ __align__(256) __half g_attn0[(size_t)MT*ATW];
__device__ __align__(256) __half g_attn1[(size_t)MT*ATW];
__device__ __align__(256) __half g_zcat[(size_t)MT*2*Cc];
__device__ __align__(256) __half g_wh[655360];
__device__ float g_psum[2*Bb*NT*NBLK];
__device__ float g_rowinv[2*Bb*NT];
__device__ float g_fused[(size_t)Bb*Cc*NT];

__device__ __forceinline__ void cpa16u(uint32_t smem_dst, const void* gsrc) {
    asm volatile("cp.async.cg.shared.global [%0], [%1], 16;" :: "r"(smem_dst), "l"(gsrc));
}
__device__ __forceinline__ void ldsm_x4u(unsigned* r, uint32_t s) {
    asm volatile("ldmatrix.sync.aligned.m8n8.x4.shared.b16 {%0,%1,%2,%3}, [%4];"
                 : "=r"(r[0]), "=r"(r[1]), "=r"(r[2]), "=r"(r[3]) : "r"(s));
}
__device__ __forceinline__ void ldsm_x4tu(unsigned* r, uint32_t s) {
    asm volatile("ldmatrix.sync.aligned.m8n8.x4.trans.shared.b16 {%0,%1,%2,%3}, [%4];"
                 : "=r"(r[0]), "=r"(r[1]), "=r"(r[2]), "=r"(r[3]) : "r"(s));
}
__device__ __forceinline__ void hmma(float* d, const unsigned* a, unsigned b0, unsigned b1) {
    asm volatile("mma.sync.aligned.m16n8k16.row.col.f32.f16.f16.f32 "
                 "{%0,%1,%2,%3}, {%4,%5,%6,%7}, {%8,%9}, {%0,%1,%2,%3};"
                 : "+f"(d[0]), "+f"(d[1]), "+f"(d[2]), "+f"(d[3])
                 : "r"(a[0]), "r"(a[1]), "r"(a[2]), "r"(a[3]), "r"(b0), "r"(b1));
}

// ======== fp16 GEMM core: 64(M) x 128(N) block, 128 threads, 3-stage pipeline ========
template<int BTRANS>
__device__ __forceinline__ void gemm64_fp16(
    const __half* __restrict__ A, int lda,
    const __half* __restrict__ B, int ldb,
    int K, float acc[2][8][4])
{
    __shared__ __align__(16) __half As[3][ASW];
    __shared__ __align__(16) __half Bs[3][BSW];
    const int tid = threadIdx.x, lane = tid & 31, warp = tid >> 5;
    const int wm = (warp >> 1) * 32, wn = (warp & 1) * 64;

    const int a_row = tid >> 2, a_kg = (tid & 3) * 8;
    const int bt_row = tid >> 4, bt_nc = (tid & 15) * 8;
    const uint32_t as_b = (uint32_t)__cvta_generic_to_shared(&As[0][0]);
    const uint32_t bs_b = (uint32_t)__cvta_generic_to_shared(&Bs[0][0]);
    const uint32_t a_d0 = as_b + 2 * (a_row * SA + a_kg);
    const uint32_t a_d1 = a_d0 + 2 * (32 * SA);
    uint32_t b_d0, b_d1, b_d2, b_d3;
    if (BTRANS) {
        b_d0 = bs_b + 2 * (bt_row * SN + bt_nc);
        b_d1 = b_d0 + 2 * (8 * SN);
        b_d2 = b_d0 + 2 * (16 * SN);
        b_d3 = b_d0 + 2 * (24 * SN);
    } else {
        b_d0 = bs_b + 2 * (a_row * SA + a_kg);
        b_d1 = b_d0 + 2 * (32 * SA);
        b_d2 = b_d0 + 2 * (64 * SA);
        b_d3 = b_d0 + 2 * (96 * SA);
    }

    auto issue = [&](int ci) {
        int k0 = ci * 32;
        uint32_t ao = (ci % 3) * (ASW * 2), bo = (ci % 3) * (BSW * 2);
        cpa16u(a_d0 + ao, A + (size_t)a_row * lda + k0 + a_kg);
        cpa16u(a_d1 + ao, A + (size_t)(a_row + 32) * lda + k0 + a_kg);
        if (BTRANS) {
            const __half* gb = B + (size_t)(k0 + bt_row) * ldb + bt_nc;
            cpa16u(b_d0 + bo, gb);
            cpa16u(b_d1 + bo, gb + (size_t)8 * ldb);
            cpa16u(b_d2 + bo, gb + (size_t)16 * ldb);
            cpa16u(b_d3 + bo, gb + (size_t)24 * ldb);
        } else {
            const __half* gb = B + (size_t)a_row * ldb + k0 + a_kg;
            cpa16u(b_d0 + bo, gb);
            cpa16u(b_d1 + bo, gb + (size_t)32 * ldb);
            cpa16u(b_d2 + bo, gb + (size_t)64 * ldb);
            cpa16u(b_d3 + bo, gb + (size_t)96 * ldb);
        }
        asm volatile("cp.async.commit_group;");
    };

    const uint32_t a_f0 = as_b + 2 * ((wm + (lane & 15)) * SA + (lane >> 4) * 8);
    const uint32_t a_f1 = a_f0 + 2 * (16 * SA);
    uint32_t b_f[4];
    if (BTRANS) {
        uint32_t base = bs_b + 2 * (((lane & 7) + 8 * (lane >> 4)) * SN
                                    + wn + 8 * ((lane >> 3) & 1));
#pragma unroll
        for (int gi = 0; gi < 4; gi++) b_f[gi] = base + 2 * (gi * 16);
    } else {
        uint32_t base = bs_b + 2 * ((wn + (lane & 15)) * SA + (lane >> 4) * 8);
#pragma unroll
        for (int gi = 0; gi < 4; gi++) b_f[gi] = base + 2 * (gi * 16 * SA);
    }

    const int nk = K / 32;
    issue(0);
    if (nk > 1) issue(1);
    for (int i = 0; i < nk; i++) {
        if (i + 1 < nk) asm volatile("cp.async.wait_group 1;");
        else            asm volatile("cp.async.wait_group 0;");
        __syncthreads();
        if (i + 2 < nk) issue(i + 2);
        const uint32_t ao = (i % 3) * (ASW * 2), bo = (i % 3) * (BSW * 2);
#pragma unroll
        for (int s = 0; s < 2; s++) {
            const int kk = s * 16;
            unsigned a[2][4], bf[4][4];
            ldsm_x4u(a[0], a_f0 + ao + 2 * kk);
            ldsm_x4u(a[1], a_f1 + ao + 2 * kk);
#pragma unroll
            for (int gi = 0; gi < 4; gi++) {
                if (BTRANS) ldsm_x4tu(bf[gi], b_f[gi] + bo + 2 * (kk * SN));
                else        ldsm_x4u (bf[gi], b_f[gi] + bo + 2 * kk);
            }
#pragma unroll
            for (int mi = 0; mi < 2; mi++)
#pragma unroll
                for (int ni = 0; ni < 8; ni++) {
                    int gi = ni >> 1, hi = ni & 1;
                    hmma(acc[mi][ni], a[mi], bf[gi][hi], bf[gi][hi + 2]);
                }
        }
    }
}

// ---------------- weight prep ----------------
__global__ void wprep_kernel(
    const float* w0, const float* w1, const float* w2, const float* w3,
    const float* w4, const float* w5, const float* w6, const float* w7, const float* w8)
{
    int seg = blockIdx.y;
    int idx = blockIdx.x * 256 + threadIdx.x;
    int size = (seg == 8) ? 131072 : 65536;
    if (idx >= size) return;
    const float* src;
    switch (seg) {
        case 0: src = w0; break; case 1: src = w1; break; case 2: src = w2; break;
        case 3: src = w3; break; case 4: src = w4; break; case 5: src = w5; break;
        case 6: src = w6; break; case 7: src = w7; break; default: src = w8; break;
    }
    g_wh[seg * 65536 + idx] = __float2half_rn(src[idx]);
}

// ---------------- downsample ----------------
__global__ void ds_kernel(const float* __restrict__ zr, const float* __restrict__ zi) {
    __shared__ float t[32][33];
    int b = blockIdx.z, n0 = blockIdx.x * 32, c0 = blockIdx.y * 32;
    int tx = threadIdx.x, ty = threadIdx.y;
#pragma unroll
    for (int m = 0; m < 2; m++) {
        const float* src = m ? zi : zr;
        __half* dst = m ? g_ds_ir : g_ds_rgb;
        if (m) __syncthreads();
#pragma unroll
        for (int i = 0; i < 4; i++) {
            int n = n0 + tx, c = c0 + ty + 8 * i;
            int ho = n / WDs, wo = n % WDs;
            const float* p = src + ((size_t)(b * Cc + c) * HH + 4 * ho + 1) * WW + 4 * wo + 1;
            t[tx][ty + 8 * i] = 0.25f * (p[0] + p[1] + p[WW] + p[WW + 1]);
        }
        __syncthreads();
#pragma unroll
        for (int i = 0; i < 4; i++) {
            int n = n0 + ty + 8 * i, c = c0 + tx;
            dst[((size_t)b * NT + n) * Cc + c] = __float2half_rn(t[ty + 8 * i][tx]);
        }
    }
}

// ---------------- projections ----------------
__global__ void __launch_bounds__(128) proj_gemm(
    const float* __restrict__ bq_rgb, const float* __restrict__ bk_ir,
    const float* __restrict__ bv_ir,  const float* __restrict__ bq_ir,
    const float* __restrict__ bk_rgb, const float* __restrict__ bv_rgb)
{
    int b = blockIdx.x / 25, mloc = (blockIdx.x % 25) * 64;
    int n0 = blockIdx.y * 128, p = blockIdx.z;
    const __half* Ain = (p == 0 || p == 4 || p == 5) ? g_ds_rgb : g_ds_ir;
    const float* bias;
    switch (p) {
        case 0: bias = bq_rgb; break; case 1: bias = bk_ir;  break;
        case 2: bias = bv_ir;  break; case 3: bias = bq_ir;  break;
        case 4: bias = bk_rgb; break; default: bias = bv_rgb; break;
    }
    const __half* A = Ain + ((size_t)b * NT + mloc) * Cc;
    const __half* W = g_wh + p * 65536 + (size_t)n0 * Cc;
    float acc[2][8][4] = {};
    gemm64_fp16<0>(A, Cc, W, Cc, Cc, acc);

    const int tid = threadIdx.x, lane = tid & 31, warp = tid >> 5;
    const int wm = (warp >> 1) * 32, wn = (warp & 1) * 64;
    const int g = lane >> 2, tg = lane & 3;
    __half* out = g_tok[p] + ((size_t)b * NT + mloc) * Cc + n0;
#pragma unroll
    for (int mi = 0; mi < 2; mi++) {
        int r0 = wm + mi * 16 + g;
#pragma unroll
        for (int ni = 0; ni < 8; ni++) {
            int col = wn + ni * 8 + 2 * tg;
            float b0 = bias[n0 + col], b1 = bias[n0 + col + 1];
            *(__half2*)(out + (size_t)r0 * Cc + col) =
                __floats2half2_rn(acc[mi][ni][0] + b0, acc[mi][ni][1] + b1);
            *(__half2*)(out + (size_t)(r0 + 8) * Cc + col) =
                __floats2half2_rn(acc[mi][ni][2] + b0, acc[mi][ni][3] + b1);
        }
    }
}

// ---------------- scores ----------------
__global__ void __launch_bounds__(128) scores_gemm() {
    __shared__ float rsum[64];
    int m0 = blockIdx.x * 64, n0 = blockIdx.y * 128;
    int z = blockIdx.z, dir = z >> 3, b = z & 7;
    const __half* Aq = g_tok[dir ? 3 : 0] + ((size_t)b * NT + m0) * Cc;
    const __half* Bk = g_tok[dir ? 4 : 1] + ((size_t)b * NT + n0) * Cc;
    __half* out = (dir ? g_attn1 : g_attn0) + ((size_t)b * NT + m0) * ATW + n0;

    if (threadIdx.x < 64) rsum[threadIdx.x] = 0.f;
    float acc[2][8][4] = {};
    gemm64_fp16<0>(Aq, Cc, Bk, Cc, Cc, acc);

    const int tid = threadIdx.x, lane = tid & 31, warp = tid >> 5;
    const int wm = (warp >> 1) * 32, wn = (warp & 1) * 64;
    const int g = lane >> 2, tg = lane & 3;
#pragma unroll
    for (int mi = 0; mi < 2; mi++) {
        int r0 = wm + mi * 16 + g;
        float p0 = 0.f, p1 = 0.f;
#pragma unroll
        for (int ni = 0; ni < 8; ni++) {
            int col = wn + ni * 8 + 2 * tg;
            bool real = (n0 + col) < NT;
            float e0 = real ? __expf(acc[mi][ni][0] * 0.0625f) : 0.f;
            float e1 = real ? __expf(acc[mi][ni][1] * 0.0625f) : 0.f;
            float e2 = real ? __expf(acc[mi][ni][2] * 0.0625f) : 0.f;
            float e3 = real ? __expf(acc[mi][ni][3] * 0.0625f) : 0.f;
            *(__half2*)(out + (size_t)r0 * ATW + col) = __floats2half2_rn(e0, e1);
            *(__half2*)(out + (size_t)(r0 + 8) * ATW + col) = __floats2half2_rn(e2, e3);
            p0 += e0 + e1;
            p1 += e2 + e3;
        }
        p0 += __shfl_xor_sync(0xffffffffu, p0, 1); p0 += __shfl_xor_sync(0xffffffffu, p0, 2);
        p1 += __shfl_xor_sync(0xffffffffu, p1, 1); p1 += __shfl_xor_sync(0xffffffffu, p1, 2);
        if (tg == 0) {
            atomicAdd(&rsum[r0], p0);
            atomicAdd(&rsum[r0 + 8], p1);
        }
    }
    __syncthreads();
    if (tid < 64)
        g_psum[((size_t)z * NT + m0 + tid) * NBLK + blockIdx.y] = rsum[tid];
}

// ---------------- rowsum reduce ----------------
__global__ void rowinv_kernel() {
    int idx = blockIdx.x * blockDim.x + threadIdx.x;
    if (idx >= 2 * Bb * NT) return;
    float s = 0.f;
    const float* p = g_psum + (size_t)idx * NBLK;
#pragma unroll
    for (int j = 0; j < NBLK; j++) s += p[j];
    g_rowinv[idx] = 1.0f / s;
}

// ---------------- attn @ V: 64(M) x 256(N) block, 256 threads, P read ONCE ----------
__global__ void __launch_bounds__(256, 2) av_gemm() {
    extern __shared__ __half avs[];
    __half* As = avs;                      // [3][AV_A_ST]
    __half* Bs = avs + 3 * AV_A_ST;        // [3][AV_B_ST]
    int m0 = blockIdx.x * 64;
    int z = blockIdx.y, dir = z >> 3, b = z & 7;
    const __half* P = (dir ? g_attn1 : g_attn0) + ((size_t)b * NT + m0) * ATW;
    const __half* V = g_tok[dir ? 5 : 2] + (size_t)b * NT * Cc;    // [k][n], ldb=Cc

    const int tid = threadIdx.x, lane = tid & 31, warp = tid >> 5;
    const int wm = (warp >> 2) * 32, pn = (warp & 3) * 64;
    const int g = lane >> 2, tg = lane & 3;

    const uint32_t as_b = (uint32_t)__cvta_generic_to_shared(As);
    const uint32_t bs_b = (uint32_t)__cvta_generic_to_shared(Bs);
    const int a_row = tid >> 2, a_kg = (tid & 3) * 8;       // 64 rows x 4 chunks
    const uint32_t a_d = as_b + 2 * (a_row * SA + a_kg);
    const int b_row = tid >> 5, b_nc = (tid & 31) * 8;      // rows 0..7 (+8,16,24)
    const uint32_t b_d0 = bs_b + 2 * (b_row * SVN + b_nc);
    const uint32_t b_d1 = b_d0 + 2 * (8 * SVN);
    const uint32_t b_d2 = b_d0 + 2 * (16 * SVN);
    const uint32_t b_d3 = b_d0 + 2 * (24 * SVN);

    auto issue = [&](int ci) {
        int k0 = ci * 32;
        uint32_t ao = (ci % 3) * (AV_A_ST * 2), bo = (ci % 3) * (AV_B_ST * 2);
        cpa16u(a_d + ao, P + (size_t)a_row * ATW + k0 + a_kg);
        const __half* gb = V + (size_t)(k0 + b_row) * Cc + b_nc;
        cpa16u(b_d0 + bo, gb);
        cpa16u(b_d1 + bo, gb + (size_t)8 * Cc);
        cpa16u(b_d2 + bo, gb + (size_t)16 * Cc);
        cpa16u(b_d3 + bo, gb + (size_t)24 * Cc);
        asm volatile("cp.async.commit_group;");
    };

    const uint32_t a_f0 = as_b + 2 * ((wm + (lane & 15)) * SA + (lane >> 4) * 8);
    const uint32_t a_f1 = a_f0 + 2 * (16 * SA);
    uint32_t b_f[4];
    {
        uint32_t base = bs_b + 2 * (((lane & 7) + 8 * (lane >> 4)) * SVN
                                    + pn + 8 * ((lane >> 3) & 1));
#pragma unroll
        for (int gi = 0; gi < 4; gi++) b_f[gi] = base + 2 * (gi * 16);
    }

    float acc[2][8][4] = {};
    const int nk = ATW / 32;   // 52
    issue(0); issue(1);
    for (int i = 0; i < nk; i++) {
        if (i + 1 < nk) asm volatile("cp.async.wait_group 1;");
        else            asm volatile("cp.async.wait_group 0;");
        __syncthreads();
        if (i + 2 < nk) issue(i + 2);
        const uint32_t ao = (i % 3) * (AV_A_ST * 2), bo = (i % 3) * (AV_B_ST * 2);
#pragma unroll
        for (int s = 0; s < 2; s++) {
            const int kk = s * 16;
            unsigned a[2][4], bf[4][4];
            ldsm_x4u(a[0], a_f0 + ao + 2 * kk);
            ldsm_x4u(a[1], a_f1 + ao + 2 * kk);
#pragma unroll
            for (int gi = 0; gi < 4; gi++) ldsm_x4tu(bf[gi], b_f[gi] + bo + 2 * (kk * SVN));
#pragma unroll
            for (int mi = 0; mi < 2; mi++)
#pragma unroll
                for (int ni = 0; ni < 8; ni++) {
                    int gi = ni >> 1, hi = ni & 1;
                    hmma(acc[mi][ni], a[mi], bf[gi][hi], bf[gi][hi + 2]);
                }
        }
    }

    __half* out = g_zcat + ((size_t)b * NT + m0) * 2 * Cc + dir * Cc + pn;
    const float* rinv = g_rowinv + (size_t)z * NT + m0;
#pragma unroll
    for (int mi = 0; mi < 2; mi++) {
        int r0 = wm + mi * 16 + g;
        float i0 = rinv[r0], i1 = rinv[r0 + 8];
#pragma unroll
        for (int ni = 0; ni < 8; ni++) {
            int col = ni * 8 + 2 * tg;
            *(__half2*)(out + (size_t)r0 * 2 * Cc + col) =
                __floats2half2_rn(acc[mi][ni][0] * i0, acc[mi][ni][1] * i0);
            *(__half2*)(out + (size_t)(r0 + 8) * 2 * Cc + col) =
                __floats2half2_rn(acc[mi][ni][2] * i1, acc[mi][ni][3] * i1);
        }
    }
}

// ======== fused epilogue: 3 GEMMs + gate + transpose -> g_fused ========
__global__ void __launch_bounds__(128) gatefuse_kernel(
    const float* __restrict__ brgb, const float* __restrict__ bir,
    const float* __restrict__ bz,
    const int* __restrict__ time_idx, const float* __restrict__ temb)
{
    __shared__ __align__(16) __half As[3][GSW];
    __shared__ __align__(16) __half Bzs[3][GSW];
    __shared__ __align__(16) __half Bhs[3][GSW];
    __shared__ float tb[64][65];

    const int m0 = blockIdx.x * 64, n0 = blockIdx.y * 64;
    const __half* A  = g_zcat + (size_t)m0 * 2 * Cc;
    const __half* Wz = g_wh + 524288 + (size_t)n0 * 512;
    const __half* Wr = g_wh + 6 * 65536 + (size_t)n0 * 256;
    const __half* Wi = g_wh + 7 * 65536 + (size_t)n0 * 256;

    const int tid = threadIdx.x, lane = tid & 31, warp = tid >> 5;
    const int wm = (warp >> 1) * 32, wn = (warp & 1) * 32;
    const int g = lane >> 2, tg = lane & 3;

    const int row = tid >> 2, kg = (tid & 3) * 8;
    const uint32_t as_b  = (uint32_t)__cvta_generic_to_shared(&As[0][0]);
    const uint32_t bzs_b = (uint32_t)__cvta_generic_to_shared(&Bzs[0][0]);
    const uint32_t bhs_b = (uint32_t)__cvta_generic_to_shared(&Bhs[0][0]);
    const uint32_t a_d0  = as_b  + 2 * (row * SA + kg), a_d1  = a_d0  + 2 * (32 * SA);
    const uint32_t bz_d0 = bzs_b + 2 * (row * SA + kg), bz_d1 = bz_d0 + 2 * (32 * SA);
    const uint32_t bh_d0 = bhs_b + 2 * (row * SA + kg), bh_d1 = bh_d0 + 2 * (32 * SA);

    auto issue = [&](int ci) {
        int k0 = ci * 32;
        uint32_t off = (ci % 3) * (GSW * 2);
        cpa16u(a_d0 + off, A + (size_t)row * 512 + k0 + kg);
        cpa16u(a_d1 + off, A + (size_t)(row + 32) * 512 + k0 + kg);
        cpa16u(bz_d0 + off, Wz + (size_t)row * 512 + k0 + kg);
        cpa16u(bz_d1 + off, Wz + (size_t)(row + 32) * 512 + k0 + kg);
        const __half* Wh = (k0 < 256) ? (Wr + k0) : (Wi + k0 - 256);
        cpa16u(bh_d0 + off, Wh + (size_t)row * 256 + kg);
        cpa16u(bh_d1 + off, Wh + (size_t)(row + 32) * 256 + kg);
        asm volatile("cp.async.commit_group;");
    };

    const uint32_t a_f0  = as_b  + 2 * ((wm + (lane & 15)) * SA + (lane >> 4) * 8);
    const uint32_t a_f1  = a_f0 + 2 * (16 * SA);
    const uint32_t bz_f0 = bzs_b + 2 * ((wn + (lane & 15)) * SA + (lane >> 4) * 8);
    const uint32_t bz_f1 = bz_f0 + 2 * (16 * SA);
    const uint32_t bh_f0 = bhs_b + 2 * ((wn + (lane & 15)) * SA + (lane >> 4) * 8);
    const uint32_t bh_f1 = bh_f0 + 2 * (16 * SA);

    float acc_z[2][4][4] = {}, acc_hr[2][4][4] = {}, acc_hi[2][4][4] = {};

    issue(0); issue(1);
    for (int i = 0; i < 16; i++) {
        if (i + 1 < 16) asm volatile("cp.async.wait_group 1;");
        else            asm volatile("cp.async.wait_group 0;");
        __syncthreads();
        if (i + 2 < 16) issue(i + 2);
        const uint32_t off = (i % 3) * (GSW * 2);
#pragma unroll
        for (int s = 0; s < 2; s++) {
            const uint32_t ko = off + 2 * (s * 16);
            unsigned a[2][4], zf[2][4], hf[2][4];
            ldsm_x4u(a[0], a_f0 + ko);  ldsm_x4u(a[1], a_f1 + ko);
            ldsm_x4u(zf[0], bz_f0 + ko); ldsm_x4u(zf[1], bz_f1 + ko);
            ldsm_x4u(hf[0], bh_f0 + ko); ldsm_x4u(hf[1], bh_f1 + ko);
#pragma unroll
            for (int mi = 0; mi < 2; mi++)
#pragma unroll
                for (int nj = 0; nj < 4; nj++) {
                    int gi = nj >> 1, hi = nj & 1;
                    hmma(acc_z[mi][nj], a[mi], zf[gi][hi], zf[gi][hi + 2]);
                }
            if (i < 8) {
#pragma unroll
                for (int mi = 0; mi < 2; mi++)
#pragma unroll
                    for (int nj = 0; nj < 4; nj++) {
                        int gi = nj >> 1, hi = nj & 1;
                        hmma(acc_hr[mi][nj], a[mi], hf[gi][hi], hf[gi][hi + 2]);
                    }
            } else {
#pragma unroll
                for (int mi = 0; mi < 2; mi++)
#pragma unroll
                    for (int nj = 0; nj < 4; nj++) {
                        int gi = nj >> 1, hi = nj & 1;
                        hmma(acc_hi[mi][nj], a[mi], hf[gi][hi], hf[gi][hi + 2]);
                    }
            }
        }
    }

    const int bI = m0 / NT, nt0 = m0 % NT;
    const int ti = time_idx[bI];
#pragma unroll
    for (int mi = 0; mi < 2; mi++)
#pragma unroll
        for (int nj = 0; nj < 4; nj++)
#pragma unroll
            for (int e = 0; e < 4; e++) {
                int r = wm + mi * 16 + g + ((e >> 1) ? 8 : 0);
                int c = wn + nj * 8 + 2 * tg + (e & 1);
                float hr = tanhf(acc_hr[mi][nj][e] + brgb[n0 + c]);
                float hi = tanhf(acc_hi[mi][nj][e] + bir[n0 + c]);
                float zb = 1.0f / (1.0f + __expf(-(acc_z[mi][nj][e] + bz[n0 + c])));
                float zg = 1.0f / (1.0f + __expf(-(zb + temb[ti * Cc + n0 + c])));
                tb[r][c] = zg * hr + (1.0f - zg) * hi;
            }
    __syncthreads();
#pragma unroll
    for (int q0 = 0; q0 < 8; q0++) {
        int q = tid + q0 * 128;
        int c = q >> 4, ch = (q & 15) * 4;
        float4 v = make_float4(tb[ch][c], tb[ch + 1][c], tb[ch + 2][c], tb[ch + 3][c]);
        *(float4*)(g_fused + ((size_t)bI * Cc + n0 + c) * NT + nt0 + ch) = v;
    }
}

// ---------------- bilinear upsample 40 -> 160, 4 outputs per thread ----------------
__global__ void upsample_kernel(float* __restrict__ out) {
    int idx = blockIdx.x * blockDim.x + threadIdx.x;
    if (idx >= Bb*Cc*HH*(WW/4)) return;
    int wq = idx % (WW/4);
    int h  = (idx / (WW/4)) % HH;
    int bc = idx / (HH * (WW/4));
    float sh = fmaxf(h * 0.25f - 0.375f, 0.0f);
    int h0 = (int)sh; float fh = sh - (float)h0; int h1 = min(h0 + 1, HDs - 1);
    const float* p0 = g_fused + (size_t)bc * NT + h0 * WDs;
    const float* p1 = g_fused + (size_t)bc * NT + h1 * WDs;
    float r[4];
#pragma unroll
    for (int j = 0; j < 4; j++) {
        int w = wq * 4 + j;
        float sw = fmaxf(w * 0.25f - 0.375f, 0.0f);
        int w0 = (int)sw; float fw = sw - (float)w0; int w1 = min(w0 + 1, WDs - 1);
        float top = p0[w0] * (1.0f - fw) + p0[w1] * fw;
        float bot = p1[w0] * (1.0f - fw) + p1[w1] * fw;
        r[j] = top * (1.0f - fh) + bot * fh;
    }
    *(float4*)(out + ((size_t)bc * HH + h) * WW + wq * 4) = make_float4(r[0], r[1], r[2], r[3]);
}

extern "C" void kernel_launch(void* const* d_in, const int* in_sizes, int n_in,
                              void* d_out, int out_size) {
    const float* z_rgb  = (const float*)d_in[0];
    const float* z_ir   = (const float*)d_in[1];
    const int*   tidx   = (const int*)  d_in[2];
    const float* Wq_rgb = (const float*)d_in[3],  *bq_rgb = (const float*)d_in[4];
    const float* Wk_ir  = (const float*)d_in[5],  *bk_ir  = (const float*)d_in[6];
    const float* Wv_ir  = (const float*)d_in[7],  *bv_ir  = (const float*)d_in[8];
    const float* Wq_ir  = (const float*)d_in[9],  *bq_ir  = (const float*)d_in[10];
    const float* Wk_rgb = (const float*)d_in[11], *bk_rgb = (const float*)d_in[12];
    const float* Wv_rgb = (const float*)d_in[13], *bv_rgb = (const float*)d_in[14];
    const float* Wrgb   = (const float*)d_in[15], *brgb   = (const float*)d_in[16];
    const float* Wir    = (const float*)d_in[17], *bir    = (const float*)d_in[18];
    const float* Wz     = (const float*)d_in[19], *bz     = (const float*)d_in[20];
    const float* temb   = (const float*)d_in[21];

    static bool attr_done = false;
    if (!attr_done) {
        cudaFuncSetAttribute(av_gemm, cudaFuncAttributeMaxDynamicSharedMemorySize, AV_SMEM);
        attr_done = true;
    }

    wprep_kernel<<<dim3(512, 9), 256>>>(Wq_rgb, Wk_ir, Wv_ir, Wq_ir, Wk_rgb, Wv_rgb,
                                        Wrgb, Wir, Wz);
    ds_kernel<<<dim3(50, 8, 8), dim3(32, 8)>>>(z_rgb, z_ir);
    proj_gemm<<<dim3(200, 2, 6), 128>>>(bq_rgb, bk_ir, bv_ir, bq_ir, bk_rgb, bv_rgb);
    scores_gemm<<<dim3(25, NBLK, 16), 128>>>();
    rowinv_kernel<<<(2*Bb*NT + 255) / 256, 256>>>();
    av_gemm<<<dim3(25, 16), 256, AV_SMEM>>>();
    gatefuse_kernel<<<dim3(200, 4), 128>>>(brgb, bir, bz, tidx, temb);
    upsample_kernel<<<(Bb*Cc*HH*(WW/4) + 255) / 256, 256>>>((float*)d_out);
}

// round 15
// speedup vs baseline: 1.2963x; 1.0282x over previous
#include <cuda_runtime.h>
#include <cuda_fp16.h>
#include <math.h>
#include <float.h>
#include <stdint.h>

#define Bb  8
#define Cc  256
#define HH  160
#define WW  160
#define HDs 40
#define WDs 40
#define NT  1600
#define MT  (Bb*NT)
#define ATW 1664
#define NBLK 13
#define SA  40              // smem row stride (halves) for [r][k] tiles
#define SVN 264             // smem row stride (halves) for [k][n] tiles, n-width 256
#define ASW (64*SA)
#define BSW 5120
#define GSW (64*SA)
// av (64x256): 3 stages A(64*SA) + B(32*SVN)
#define AV_A_ST (64*SA)
#define AV_B_ST (32*SVN)
#define AV_SMEM ((3*(AV_A_ST + AV_B_ST)) * 2)   // 66048 B
// scores (128x128): 3 stages A(128*SA) + B(128*SA)
#define SC_ST (128*SA)
#define SC_SMEM ((6*SC_ST) * 2)                 // 61440 B

// ---------------- static scratch ----------------
__device__ __align__(256) __half g_ds_rgb[(size_t)Bb*NT*Cc];
__device__ __align__(256) __half g_ds_ir [(size_t)Bb*NT*Cc];
__device__ __align__(256) __half g_tok[6][(size_t)(MT+64)*Cc];
__device__ __align__(256) __half g_attn0[(size_t)MT*ATW];
__device__ __align__(256) __half g_attn1[(size_t)MT*ATW];
__device__ __align__(256) __half g_zcat[(size_t)MT*2*Cc];
__device__ __align__(256) __half g_wh[655360];
__device__ float g_psum[2*Bb*NT*NBLK];
__device__ float g_rowinv[2*Bb*NT];
__device__ float g_fused[(size_t)Bb*Cc*NT];

__device__ __forceinline__ void cpa16u(uint32_t smem_dst, const void* gsrc) {
    asm volatile("cp.async.cg.shared.global [%0], [%1], 16;" :: "r"(smem_dst), "l"(gsrc));
}
__device__ __forceinline__ void ldsm_x4u(unsigned* r, uint32_t s) {
    asm volatile("ldmatrix.sync.aligned.m8n8.x4.shared.b16 {%0,%1,%2,%3}, [%4];"
                 : "=r"(r[0]), "=r"(r[1]), "=r"(r[2]), "=r"(r[3]) : "r"(s));
}
__device__ __forceinline__ void ldsm_x4tu(unsigned* r, uint32_t s) {
    asm volatile("ldmatrix.sync.aligned.m8n8.x4.trans.shared.b16 {%0,%1,%2,%3}, [%4];"
                 : "=r"(r[0]), "=r"(r[1]), "=r"(r[2]), "=r"(r[3]) : "r"(s));
}
__device__ __forceinline__ void hmma(float* d, const unsigned* a, unsigned b0, unsigned b1) {
    asm volatile("mma.sync.aligned.m16n8k16.row.col.f32.f16.f16.f32 "
                 "{%0,%1,%2,%3}, {%4,%5,%6,%7}, {%8,%9}, {%0,%1,%2,%3};"
                 : "+f"(d[0]), "+f"(d[1]), "+f"(d[2]), "+f"(d[3])
                 : "r"(a[0]), "r"(a[1]), "r"(a[2]), "r"(a[3]), "r"(b0), "r"(b1));
}

// ======== fp16 GEMM core: 64(M) x 128(N) block, 128 threads, 3-stage ========
__device__ __forceinline__ void gemm64_fp16(
    const __half* __restrict__ A, int lda,
    const __half* __restrict__ B, int ldb,
    int K, float acc[2][8][4])
{
    __shared__ __align__(16) __half As[3][ASW];
    __shared__ __align__(16) __half Bs[3][BSW];
    const int tid = threadIdx.x, lane = tid & 31, warp = tid >> 5;
    const int wm = (warp >> 1) * 32, wn = (warp & 1) * 64;

    const int a_row = tid >> 2, a_kg = (tid & 3) * 8;
    const uint32_t as_b = (uint32_t)__cvta_generic_to_shared(&As[0][0]);
    const uint32_t bs_b = (uint32_t)__cvta_generic_to_shared(&Bs[0][0]);
    const uint32_t a_d0 = as_b + 2 * (a_row * SA + a_kg);
    const uint32_t a_d1 = a_d0 + 2 * (32 * SA);
    const uint32_t b_d0 = bs_b + 2 * (a_row * SA + a_kg);
    const uint32_t b_d1 = b_d0 + 2 * (32 * SA);
    const uint32_t b_d2 = b_d0 + 2 * (64 * SA);
    const uint32_t b_d3 = b_d0 + 2 * (96 * SA);

    auto issue = [&](int ci) {
        int k0 = ci * 32;
        uint32_t ao = (ci % 3) * (ASW * 2), bo = (ci % 3) * (BSW * 2);
        cpa16u(a_d0 + ao, A + (size_t)a_row * lda + k0 + a_kg);
        cpa16u(a_d1 + ao, A + (size_t)(a_row + 32) * lda + k0 + a_kg);
        const __half* gb = B + (size_t)a_row * ldb + k0 + a_kg;
        cpa16u(b_d0 + bo, gb);
        cpa16u(b_d1 + bo, gb + (size_t)32 * ldb);
        cpa16u(b_d2 + bo, gb + (size_t)64 * ldb);
        cpa16u(b_d3 + bo, gb + (size_t)96 * ldb);
        asm volatile("cp.async.commit_group;");
    };

    const uint32_t a_f0 = as_b + 2 * ((wm + (lane & 15)) * SA + (lane >> 4) * 8);
    const uint32_t a_f1 = a_f0 + 2 * (16 * SA);
    uint32_t b_f[4];
    {
        uint32_t base = bs_b + 2 * ((wn + (lane & 15)) * SA + (lane >> 4) * 8);
#pragma unroll
        for (int gi = 0; gi < 4; gi++) b_f[gi] = base + 2 * (gi * 16 * SA);
    }

    const int nk = K / 32;
    issue(0);
    if (nk > 1) issue(1);
    for (int i = 0; i < nk; i++) {
        if (i + 1 < nk) asm volatile("cp.async.wait_group 1;");
        else            asm volatile("cp.async.wait_group 0;");
        __syncthreads();
        if (i + 2 < nk) issue(i + 2);
        const uint32_t ao = (i % 3) * (ASW * 2), bo = (i % 3) * (BSW * 2);
#pragma unroll
        for (int s = 0; s < 2; s++) {
            const int kk = s * 16;
            unsigned a[2][4], bf[4][4];
            ldsm_x4u(a[0], a_f0 + ao + 2 * kk);
            ldsm_x4u(a[1], a_f1 + ao + 2 * kk);
#pragma unroll
            for (int gi = 0; gi < 4; gi++) ldsm_x4u(bf[gi], b_f[gi] + bo + 2 * kk);
#pragma unroll
            for (int mi = 0; mi < 2; mi++)
#pragma unroll
                for (int ni = 0; ni < 8; ni++) {
                    int gi = ni >> 1, hi = ni & 1;
                    hmma(acc[mi][ni], a[mi], bf[gi][hi], bf[gi][hi + 2]);
                }
        }
    }
}

// ---------------- weight prep ----------------
__global__ void wprep_kernel(
    const float* w0, const float* w1, const float* w2, const float* w3,
    const float* w4, const float* w5, const float* w6, const float* w7, const float* w8)
{
    int seg = blockIdx.y;
    int idx = blockIdx.x * 256 + threadIdx.x;
    int size = (seg == 8) ? 131072 : 65536;
    if (idx >= size) return;
    const float* src;
    switch (seg) {
        case 0: src = w0; break; case 1: src = w1; break; case 2: src = w2; break;
        case 3: src = w3; break; case 4: src = w4; break; case 5: src = w5; break;
        case 6: src = w6; break; case 7: src = w7; break; default: src = w8; break;
    }
    g_wh[seg * 65536 + idx] = __float2half_rn(src[idx]);
}

// ---------------- downsample ----------------
__global__ void ds_kernel(const float* __restrict__ zr, const float* __restrict__ zi) {
    __shared__ float t[32][33];
    int b = blockIdx.z, n0 = blockIdx.x * 32, c0 = blockIdx.y * 32;
    int tx = threadIdx.x, ty = threadIdx.y;
#pragma unroll
    for (int m = 0; m < 2; m++) {
        const float* src = m ? zi : zr;
        __half* dst = m ? g_ds_ir : g_ds_rgb;
        if (m) __syncthreads();
#pragma unroll
        for (int i = 0; i < 4; i++) {
            int n = n0 + tx, c = c0 + ty + 8 * i;
            int ho = n / WDs, wo = n % WDs;
            const float* p = src + ((size_t)(b * Cc + c) * HH + 4 * ho + 1) * WW + 4 * wo + 1;
            t[tx][ty + 8 * i] = 0.25f * (p[0] + p[1] + p[WW] + p[WW + 1]);
        }
        __syncthreads();
#pragma unroll
        for (int i = 0; i < 4; i++) {
            int n = n0 + ty + 8 * i, c = c0 + tx;
            dst[((size_t)b * NT + n) * Cc + c] = __float2half_rn(t[ty + 8 * i][tx]);
        }
    }
}

// ---------------- projections ----------------
__global__ void __launch_bounds__(128) proj_gemm(
    const float* __restrict__ bq_rgb, const float* __restrict__ bk_ir,
    const float* __restrict__ bv_ir,  const float* __restrict__ bq_ir,
    const float* __restrict__ bk_rgb, const float* __restrict__ bv_rgb)
{
    int b = blockIdx.x / 25, mloc = (blockIdx.x % 25) * 64;
    int n0 = blockIdx.y * 128, p = blockIdx.z;
    const __half* Ain = (p == 0 || p == 4 || p == 5) ? g_ds_rgb : g_ds_ir;
    const float* bias;
    switch (p) {
        case 0: bias = bq_rgb; break; case 1: bias = bk_ir;  break;
        case 2: bias = bv_ir;  break; case 3: bias = bq_ir;  break;
        case 4: bias = bk_rgb; break; default: bias = bv_rgb; break;
    }
    const __half* A = Ain + ((size_t)b * NT + mloc) * Cc;
    const __half* W = g_wh + p * 65536 + (size_t)n0 * Cc;
    float acc[2][8][4] = {};
    gemm64_fp16(A, Cc, W, Cc, Cc, acc);

    const int tid = threadIdx.x, lane = tid & 31, warp = tid >> 5;
    const int wm = (warp >> 1) * 32, wn = (warp & 1) * 64;
    const int g = lane >> 2, tg = lane & 3;
    __half* out = g_tok[p] + ((size_t)b * NT + mloc) * Cc + n0;
#pragma unroll
    for (int mi = 0; mi < 2; mi++) {
        int r0 = wm + mi * 16 + g;
#pragma unroll
        for (int ni = 0; ni < 8; ni++) {
            int col = wn + ni * 8 + 2 * tg;
            float b0 = bias[n0 + col], b1 = bias[n0 + col + 1];
            *(__half2*)(out + (size_t)r0 * Cc + col) =
                __floats2half2_rn(acc[mi][ni][0] + b0, acc[mi][ni][1] + b1);
            *(__half2*)(out + (size_t)(r0 + 8) * Cc + col) =
                __floats2half2_rn(acc[mi][ni][2] + b0, acc[mi][ni][3] + b1);
        }
    }
}

// ---------------- scores v2: 128(M) x 128(N), 256 threads, masked M pad ----------------
__global__ void __launch_bounds__(256, 2) scores_gemm() {
    extern __shared__ __half ss[];
    __half* As = ss;                    // [3][SC_ST]
    __half* Bs = ss + 3 * SC_ST;        // [3][SC_ST]
    __shared__ float rsum[128];
    int m0 = blockIdx.x * 128, n0 = blockIdx.y * 128;
    int z = blockIdx.z, dir = z >> 3, b = z & 7;
    const __half* Aq = g_tok[dir ? 3 : 0] + ((size_t)b * NT + m0) * Cc;
    const __half* Bk = g_tok[dir ? 4 : 1] + ((size_t)b * NT + n0) * Cc;
    __half* out = (dir ? g_attn1 : g_attn0) + ((size_t)b * NT + m0) * ATW + n0;

    const int tid = threadIdx.x, lane = tid & 31, warp = tid >> 5;
    const int wm = (warp >> 1) * 32, wn = (warp & 1) * 64;
    const int g = lane >> 2, tg = lane & 3;
    if (tid < 128) rsum[tid] = 0.f;

    const int row = tid >> 2, kg = (tid & 3) * 8;
    const uint32_t as_b = (uint32_t)__cvta_generic_to_shared(As);
    const uint32_t bs_b = (uint32_t)__cvta_generic_to_shared(Bs);
    const uint32_t a_d0 = as_b + 2 * (row * SA + kg), a_d1 = a_d0 + 2 * (64 * SA);
    const uint32_t b_d0 = bs_b + 2 * (row * SA + kg), b_d1 = b_d0 + 2 * (64 * SA);

    auto issue = [&](int ci) {
        int k0 = ci * 32;
        uint32_t off = (ci % 3) * (SC_ST * 2);
        cpa16u(a_d0 + off, Aq + (size_t)row * Cc + k0 + kg);
        cpa16u(a_d1 + off, Aq + (size_t)(row + 64) * Cc + k0 + kg);
        cpa16u(b_d0 + off, Bk + (size_t)row * Cc + k0 + kg);
        cpa16u(b_d1 + off, Bk + (size_t)(row + 64) * Cc + k0 + kg);
        asm volatile("cp.async.commit_group;");
    };

    const uint32_t a_f0 = as_b + 2 * ((wm + (lane & 15)) * SA + (lane >> 4) * 8);
    const uint32_t a_f1 = a_f0 + 2 * (16 * SA);
    uint32_t b_f[4];
    {
        uint32_t base = bs_b + 2 * ((wn + (lane & 15)) * SA + (lane >> 4) * 8);
#pragma unroll
        for (int gi = 0; gi < 4; gi++) b_f[gi] = base + 2 * (gi * 16 * SA);
    }

    float acc[2][8][4] = {};
    issue(0); issue(1);
#pragma unroll
    for (int i = 0; i < 8; i++) {
        if (i + 1 < 8) asm volatile("cp.async.wait_group 1;");
        else           asm volatile("cp.async.wait_group 0;");
        __syncthreads();
        if (i + 2 < 8) issue(i + 2);
        const uint32_t off = (i % 3) * (SC_ST * 2);
#pragma unroll
        for (int s = 0; s < 2; s++) {
            const uint32_t ko = off + 2 * (s * 16);
            unsigned a[2][4], bf[4][4];
            ldsm_x4u(a[0], a_f0 + ko);
            ldsm_x4u(a[1], a_f1 + ko);
#pragma unroll
            for (int gi = 0; gi < 4; gi++) ldsm_x4u(bf[gi], b_f[gi] + ko);
#pragma unroll
            for (int mi = 0; mi < 2; mi++)
#pragma unroll
                for (int ni = 0; ni < 8; ni++) {
                    int gi = ni >> 1, hi = ni & 1;
                    hmma(acc[mi][ni], a[mi], bf[gi][hi], bf[gi][hi + 2]);
                }
        }
    }

#pragma unroll
    for (int mi = 0; mi < 2; mi++) {
        int r0 = wm + mi * 16 + g;
        bool ok0 = (m0 + r0) < NT, ok1 = (m0 + r0 + 8) < NT;
        float p0 = 0.f, p1 = 0.f;
#pragma unroll
        for (int ni = 0; ni < 8; ni++) {
            int col = wn + ni * 8 + 2 * tg;
            bool real = (n0 + col) < NT;
            float e0 = real ? __expf(acc[mi][ni][0] * 0.0625f) : 0.f;
            float e1 = real ? __expf(acc[mi][ni][1] * 0.0625f) : 0.f;
            float e2 = real ? __expf(acc[mi][ni][2] * 0.0625f) : 0.f;
            float e3 = real ? __expf(acc[mi][ni][3] * 0.0625f) : 0.f;
            if (ok0) *(__half2*)(out + (size_t)r0 * ATW + col) = __floats2half2_rn(e0, e1);
            if (ok1) *(__half2*)(out + (size_t)(r0 + 8) * ATW + col) = __floats2half2_rn(e2, e3);
            p0 += e0 + e1;
            p1 += e2 + e3;
        }
        p0 += __shfl_xor_sync(0xffffffffu, p0, 1); p0 += __shfl_xor_sync(0xffffffffu, p0, 2);
        p1 += __shfl_xor_sync(0xffffffffu, p1, 1); p1 += __shfl_xor_sync(0xffffffffu, p1, 2);
        if (tg == 0) {
            atomicAdd(&rsum[r0], p0);
            atomicAdd(&rsum[r0 + 8], p1);
        }
    }
    __syncthreads();
    if (tid < 128 && (m0 + tid) < NT)
        g_psum[((size_t)z * NT + m0 + tid) * NBLK + blockIdx.y] = rsum[tid];
}

// ---------------- rowsum reduce ----------------
__global__ void rowinv_kernel() {
    int idx = blockIdx.x * blockDim.x + threadIdx.x;
    if (idx >= 2 * Bb * NT) return;
    float s = 0.f;
    const float* p = g_psum + (size_t)idx * NBLK;
#pragma unroll
    for (int j = 0; j < NBLK; j++) s += p[j];
    g_rowinv[idx] = 1.0f / s;
}

// ---------------- attn @ V: 64(M) x 256(N), 256 threads, P read once ----------------
__global__ void __launch_bounds__(256, 2) av_gemm() {
    extern __shared__ __half avs[];
    __half* As = avs;
    __half* Bs = avs + 3 * AV_A_ST;
    int m0 = blockIdx.x * 64;
    int z = blockIdx.y, dir = z >> 3, b = z & 7;
    const __half* P = (dir ? g_attn1 : g_attn0) + ((size_t)b * NT + m0) * ATW;
    const __half* V = g_tok[dir ? 5 : 2] + (size_t)b * NT * Cc;

    const int tid = threadIdx.x, lane = tid & 31, warp = tid >> 5;
    const int wm = (warp >> 2) * 32, pn = (warp & 3) * 64;
    const int g = lane >> 2, tg = lane & 3;

    const uint32_t as_b = (uint32_t)__cvta_generic_to_shared(As);
    const uint32_t bs_b = (uint32_t)__cvta_generic_to_shared(Bs);
    const int a_row = tid >> 2, a_kg = (tid & 3) * 8;
    const uint32_t a_d = as_b + 2 * (a_row * SA + a_kg);
    const int b_row = tid >> 5, b_nc = (tid & 31) * 8;
    const uint32_t b_d0 = bs_b + 2 * (b_row * SVN + b_nc);
    const uint32_t b_d1 = b_d0 + 2 * (8 * SVN);
    const uint32_t b_d2 = b_d0 + 2 * (16 * SVN);
    const uint32_t b_d3 = b_d0 + 2 * (24 * SVN);

    auto issue = [&](int ci) {
        int k0 = ci * 32;
        uint32_t ao = (ci % 3) * (AV_A_ST * 2), bo = (ci % 3) * (AV_B_ST * 2);
        cpa16u(a_d + ao, P + (size_t)a_row * ATW + k0 + a_kg);
        const __half* gb = V + (size_t)(k0 + b_row) * Cc + b_nc;
        cpa16u(b_d0 + bo, gb);
        cpa16u(b_d1 + bo, gb + (size_t)8 * Cc);
        cpa16u(b_d2 + bo, gb + (size_t)16 * Cc);
        cpa16u(b_d3 + bo, gb + (size_t)24 * Cc);
        asm volatile("cp.async.commit_group;");
    };

    const uint32_t a_f0 = as_b + 2 * ((wm + (lane & 15)) * SA + (lane >> 4) * 8);
    const uint32_t a_f1 = a_f0 + 2 * (16 * SA);
    uint32_t b_f[4];
    {
        uint32_t base = bs_b + 2 * (((lane & 7) + 8 * (lane >> 4)) * SVN
                                    + pn + 8 * ((lane >> 3) & 1));
#pragma unroll
        for (int gi = 0; gi < 4; gi++) b_f[gi] = base + 2 * (gi * 16);
    }

    float acc[2][8][4] = {};
    const int nk = ATW / 32;
    issue(0); issue(1);
    for (int i = 0; i < nk; i++) {
        if (i + 1 < nk) asm volatile("cp.async.wait_group 1;");
        else            asm volatile("cp.async.wait_group 0;");
        __syncthreads();
        if (i + 2 < nk) issue(i + 2);
        const uint32_t ao = (i % 3) * (AV_A_ST * 2), bo = (i % 3) * (AV_B_ST * 2);
#pragma unroll
        for (int s = 0; s < 2; s++) {
            const int kk = s * 16;
            unsigned a[2][4], bf[4][4];
            ldsm_x4u(a[0], a_f0 + ao + 2 * kk);
            ldsm_x4u(a[1], a_f1 + ao + 2 * kk);
#pragma unroll
            for (int gi = 0; gi < 4; gi++) ldsm_x4tu(bf[gi], b_f[gi] + bo + 2 * (kk * SVN));
#pragma unroll
            for (int mi = 0; mi < 2; mi++)
#pragma unroll
                for (int ni = 0; ni < 8; ni++) {
                    int gi = ni >> 1, hi = ni & 1;
                    hmma(acc[mi][ni], a[mi], bf[gi][hi], bf[gi][hi + 2]);
                }
        }
    }

    __half* out = g_zcat + ((size_t)b * NT + m0) * 2 * Cc + dir * Cc + pn;
    const float* rinv = g_rowinv + (size_t)z * NT + m0;
#pragma unroll
    for (int mi = 0; mi < 2; mi++) {
        int r0 = wm + mi * 16 + g;
        float i0 = rinv[r0], i1 = rinv[r0 + 8];
#pragma unroll
        for (int ni = 0; ni < 8; ni++) {
            int col = ni * 8 + 2 * tg;
            *(__half2*)(out + (size_t)r0 * 2 * Cc + col) =
                __floats2half2_rn(acc[mi][ni][0] * i0, acc[mi][ni][1] * i0);
            *(__half2*)(out + (size_t)(r0 + 8) * 2 * Cc + col) =
                __floats2half2_rn(acc[mi][ni][2] * i1, acc[mi][ni][3] * i1);
        }
    }
}

// ======== fused epilogue: 3 GEMMs + gate + transpose -> g_fused ========
__global__ void __launch_bounds__(128) gatefuse_kernel(
    const float* __restrict__ brgb, const float* __restrict__ bir,
    const float* __restrict__ bz,
    const int* __restrict__ time_idx, const float* __restrict__ temb)
{
    __shared__ __align__(16) __half As[3][GSW];
    __shared__ __align__(16) __half Bzs[3][GSW];
    __shared__ __align__(16) __half Bhs[3][GSW];
    __shared__ float tb[64][65];

    const int m0 = blockIdx.x * 64, n0 = blockIdx.y * 64;
    const __half* A  = g_zcat + (size_t)m0 * 2 * Cc;
    const __half* Wz = g_wh + 524288 + (size_t)n0 * 512;
    const __half* Wr = g_wh + 6 * 65536 + (size_t)n0 * 256;
    const __half* Wi = g_wh + 7 * 65536 + (size_t)n0 * 256;

    const int tid = threadIdx.x, lane = tid & 31, warp = tid >> 5;
    const int wm = (warp >> 1) * 32, wn = (warp & 1) * 32;
    const int g = lane >> 2, tg = lane & 3;

    const int row = tid >> 2, kg = (tid & 3) * 8;
    const uint32_t as_b  = (uint32_t)__cvta_generic_to_shared(&As[0][0]);
    const uint32_t bzs_b = (uint32_t)__cvta_generic_to_shared(&Bzs[0][0]);
    const uint32_t bhs_b = (uint32_t)__cvta_generic_to_shared(&Bhs[0][0]);
    const uint32_t a_d0  = as_b  + 2 * (row * SA + kg), a_d1  = a_d0  + 2 * (32 * SA);
    const uint32_t bz_d0 = bzs_b + 2 * (row * SA + kg), bz_d1 = bz_d0 + 2 * (32 * SA);
    const uint32_t bh_d0 = bhs_b + 2 * (row * SA + kg), bh_d1 = bh_d0 + 2 * (32 * SA);

    auto issue = [&](int ci) {
        int k0 = ci * 32;
        uint32_t off = (ci % 3) * (GSW * 2);
        cpa16u(a_d0 + off, A + (size_t)row * 512 + k0 + kg);
        cpa16u(a_d1 + off, A + (size_t)(row + 32) * 512 + k0 + kg);
        cpa16u(bz_d0 + off, Wz + (size_t)row * 512 + k0 + kg);
        cpa16u(bz_d1 + off, Wz + (size_t)(row + 32) * 512 + k0 + kg);
        const __half* Wh = (k0 < 256) ? (Wr + k0) : (Wi + k0 - 256);
        cpa16u(bh_d0 + off, Wh + (size_t)row * 256 + kg);
        cpa16u(bh_d1 + off, Wh + (size_t)(row + 32) * 256 + kg);
        asm volatile("cp.async.commit_group;");
    };

    const uint32_t a_f0  = as_b  + 2 * ((wm + (lane & 15)) * SA + (lane >> 4) * 8);
    const uint32_t a_f1  = a_f0 + 2 * (16 * SA);
    const uint32_t bz_f0 = bzs_b + 2 * ((wn + (lane & 15)) * SA + (lane >> 4) * 8);
    const uint32_t bz_f1 = bz_f0 + 2 * (16 * SA);
    const uint32_t bh_f0 = bhs_b + 2 * ((wn + (lane & 15)) * SA + (lane >> 4) * 8);
    const uint32_t bh_f1 = bh_f0 + 2 * (16 * SA);

    float acc_z[2][4][4] = {}, acc_hr[2][4][4] = {}, acc_hi[2][4][4] = {};

    issue(0); issue(1);
    for (int i = 0; i < 16; i++) {
        if (i + 1 < 16) asm volatile("cp.async.wait_group 1;");
        else            asm volatile("cp.async.wait_group 0;");
        __syncthreads();
        if (i + 2 < 16) issue(i + 2);
        const uint32_t off = (i % 3) * (GSW * 2);
#pragma unroll
        for (int s = 0; s < 2; s++) {
            const uint32_t ko = off + 2 * (s * 16);
            unsigned a[2][4], zf[2][4], hf[2][4];
            ldsm_x4u(a[0], a_f0 + ko);  ldsm_x4u(a[1], a_f1 + ko);
            ldsm_x4u(zf[0], bz_f0 + ko); ldsm_x4u(zf[1], bz_f1 + ko);
            ldsm_x4u(hf[0], bh_f0 + ko); ldsm_x4u(hf[1], bh_f1 + ko);
#pragma unroll
            for (int mi = 0; mi < 2; mi++)
#pragma unroll
                for (int nj = 0; nj < 4; nj++) {
                    int gi = nj >> 1, hi = nj & 1;
                    hmma(acc_z[mi][nj], a[mi], zf[gi][hi], zf[gi][hi + 2]);
                }
            if (i < 8) {
#pragma unroll
                for (int mi = 0; mi < 2; mi++)
#pragma unroll
                    for (int nj = 0; nj < 4; nj++) {
                        int gi = nj >> 1, hi = nj & 1;
                        hmma(acc_hr[mi][nj], a[mi], hf[gi][hi], hf[gi][hi + 2]);
                    }
            } else {
#pragma unroll
                for (int mi = 0; mi < 2; mi++)
#pragma unroll
                    for (int nj = 0; nj < 4; nj++) {
                        int gi = nj >> 1, hi = nj & 1;
                        hmma(acc_hi[mi][nj], a[mi], hf[gi][hi], hf[gi][hi + 2]);
                    }
            }
        }
    }

    const int bI = m0 / NT, nt0 = m0 % NT;
    const int ti = time_idx[bI];
#pragma unroll
    for (int mi = 0; mi < 2; mi++)
#pragma unroll
        for (int nj = 0; nj < 4; nj++)
#pragma unroll
            for (int e = 0; e < 4; e++) {
                int r = wm + mi * 16 + g + ((e >> 1) ? 8 : 0);
                int c = wn + nj * 8 + 2 * tg + (e & 1);
                float hr = tanhf(acc_hr[mi][nj][e] + brgb[n0 + c]);
                float hi = tanhf(acc_hi[mi][nj][e] + bir[n0 + c]);
                float zb = 1.0f / (1.0f + __expf(-(acc_z[mi][nj][e] + bz[n0 + c])));
                float zg = 1.0f / (1.0f + __expf(-(zb + temb[ti * Cc + n0 + c])));
                tb[r][c] = zg * hr + (1.0f - zg) * hi;
            }
    __syncthreads();
#pragma unroll
    for (int q0 = 0; q0 < 8; q0++) {
        int q = tid + q0 * 128;
        int c = q >> 4, ch = (q & 15) * 4;
        float4 v = make_float4(tb[ch][c], tb[ch + 1][c], tb[ch + 2][c], tb[ch + 3][c]);
        *(float4*)(g_fused + ((size_t)bI * Cc + n0 + c) * NT + nt0 + ch) = v;
    }
}

// ---------------- bilinear upsample 40 -> 160, 4 outputs per thread ----------------
__global__ void upsample_kernel(float* __restrict__ out) {
    int idx = blockIdx.x * blockDim.x + threadIdx.x;
    if (idx >= Bb*Cc*HH*(WW/4)) return;
    int wq = idx % (WW/4);
    int h  = (idx / (WW/4)) % HH;
    int bc = idx / (HH * (WW/4));
    float sh = fmaxf(h * 0.25f - 0.375f, 0.0f);
    int h0 = (int)sh; float fh = sh - (float)h0; int h1 = min(h0 + 1, HDs - 1);
    const float* p0 = g_fused + (size_t)bc * NT + h0 * WDs;
    const float* p1 = g_fused + (size_t)bc * NT + h1 * WDs;
    float r[4];
#pragma unroll
    for (int j = 0; j < 4; j++) {
        int w = wq * 4 + j;
        float sw = fmaxf(w * 0.25f - 0.375f, 0.0f);
        int w0 = (int)sw; float fw = sw - (float)w0; int w1 = min(w0 + 1, WDs - 1);
        float top = p0[w0] * (1.0f - fw) + p0[w1] * fw;
        float bot = p1[w0] * (1.0f - fw) + p1[w1] * fw;
        r[j] = top * (1.0f - fh) + bot * fh;
    }
    *(float4*)(out + ((size_t)bc * HH + h) * WW + wq * 4) = make_float4(r[0], r[1], r[2], r[3]);
}

extern "C" void kernel_launch(void* const* d_in, const int* in_sizes, int n_in,
                              void* d_out, int out_size) {
    const float* z_rgb  = (const float*)d_in[0];
    const float* z_ir   = (const float*)d_in[1];
    const int*   tidx   = (const int*)  d_in[2];
    const float* Wq_rgb = (const float*)d_in[3],  *bq_rgb = (const float*)d_in[4];
    const float* Wk_ir  = (const float*)d_in[5],  *bk_ir  = (const float*)d_in[6];
    const float* Wv_ir  = (const float*)d_in[7],  *bv_ir  = (const float*)d_in[8];
    const float* Wq_ir  = (const float*)d_in[9],  *bq_ir  = (const float*)d_in[10];
    const float* Wk_rgb = (const float*)d_in[11], *bk_rgb = (const float*)d_in[12];
    const float* Wv_rgb = (const float*)d_in[13], *bv_rgb = (const float*)d_in[14];
    const float* Wrgb   = (const float*)d_in[15], *brgb   = (const float*)d_in[16];
    const float* Wir    = (const float*)d_in[17], *bir    = (const float*)d_in[18];
    const float* Wz     = (const float*)d_in[19], *bz     = (const float*)d_in[20];
    const float* temb   = (const float*)d_in[21];

    static bool attr_done = false;
    if (!attr_done) {
        cudaFuncSetAttribute(av_gemm,     cudaFuncAttributeMaxDynamicSharedMemorySize, AV_SMEM);
        cudaFuncSetAttribute(scores_gemm, cudaFuncAttributeMaxDynamicSharedMemorySize, SC_SMEM);
        attr_done = true;
    }

    wprep_kernel<<<dim3(512, 9), 256>>>(Wq_rgb, Wk_ir, Wv_ir, Wq_ir, Wk_rgb, Wv_rgb,
                                        Wrgb, Wir, Wz);
    ds_kernel<<<dim3(50, 8, 8), dim3(32, 8)>>>(z_rgb, z_ir);
    proj_gemm<<<dim3(200, 2, 6), 128>>>(bq_rgb, bk_ir, bv_ir, bq_ir, bk_rgb, bv_rgb);
    scores_gemm<<<dim3(NBLK, NBLK, 16), 256, SC_SMEM>>>();
    rowinv_kernel<<<(2*Bb*NT + 255) / 256, 256>>>();
    av_gemm<<<dim3(25, 16), 256, AV_SMEM>>>();
    gatefuse_kernel<<<dim3(200, 4), 128>>>(brgb, bir, bz, tidx, temb);
    upsample_kernel<<<(Bb*Cc*HH*(WW/4) + 255) / 256, 256>>>((float*)d_out);
}